// round 13
// baseline (speedup 1.0000x reference)
#include <cuda_runtime.h>
#include <cuda_bf16.h>
#include <math.h>

#define BB 8
#define NN 2048
#define CC 768
#define HH 12
#define MM 1536
#define RR 512
#define NSRC 1024
#define NDST 1024
#define C3 2304

__device__ __forceinline__ float tf32r(float x) {
    unsigned r; asm("cvt.rna.tf32.f32 %0, %1;" : "=r"(r) : "f"(x));
    return __uint_as_float(r);
}
__device__ __forceinline__ void mma8(float c[4], const unsigned a[4], const unsigned b[2]) {
    asm volatile("mma.sync.aligned.m16n8k8.row.col.f32.tf32.tf32.f32 "
        "{%0,%1,%2,%3}, {%4,%5,%6,%7}, {%8,%9}, {%0,%1,%2,%3};"
        : "+f"(c[0]), "+f"(c[1]), "+f"(c[2]), "+f"(c[3])
        : "r"(a[0]), "r"(a[1]), "r"(a[2]), "r"(a[3]), "r"(b[0]), "r"(b[1]));
}
__device__ __forceinline__ void mma16bf(float c[4], const unsigned a[4], const unsigned b[2]) {
    asm volatile("mma.sync.aligned.m16n8k16.row.col.f32.bf16.bf16.f32 "
        "{%0,%1,%2,%3}, {%4,%5,%6,%7}, {%8,%9}, {%0,%1,%2,%3};"
        : "+f"(c[0]), "+f"(c[1]), "+f"(c[2]), "+f"(c[3])
        : "r"(a[0]), "r"(a[1]), "r"(a[2]), "r"(a[3]), "r"(b[0]), "r"(b[1]));
}
__device__ __forceinline__ void ldsm4(unsigned r[4], unsigned addr) {
    asm volatile("ldmatrix.sync.aligned.m8n8.x4.shared.b16 {%0,%1,%2,%3}, [%4];"
        : "=r"(r[0]), "=r"(r[1]), "=r"(r[2]), "=r"(r[3]) : "r"(addr));
}
__device__ __forceinline__ unsigned smem_u32(const void* p) {
    return (unsigned)__cvta_generic_to_shared(p);
}
__device__ __forceinline__ void cp16(unsigned d, const void* s) {
    asm volatile("cp.async.cg.shared.global [%0], [%1], 16;" :: "r"(d), "l"(s));
}
__device__ __forceinline__ void cp4(unsigned d, const void* s) {
    asm volatile("cp.async.ca.shared.global [%0], [%1], 4;" :: "r"(d), "l"(s));
}
__device__ __forceinline__ void cpcommit() { asm volatile("cp.async.commit_group;"); }
__device__ __forceinline__ void cpwait0()  { asm volatile("cp.async.wait_group 0;"); }

#define U(x) __float_as_uint(x)

// ---------------- scratch ----------------
__device__ __nv_bfloat16 g_mhib[(size_t)BB * NN * CC];
__device__ __nv_bfloat16 g_mlob[(size_t)BB * NN * CC];
__device__ float g_pmax[BB * 8 * NSRC];
__device__ int   g_pidx[BB * 8 * NSRC];
__device__ int   g_srcidx[BB * RR];
__device__ int   g_unmidx[BB * RR];
__device__ int   g_gather[BB * NSRC];
__device__ int   g_lhead[BB * NSRC];
__device__ int   g_lnext[BB * RR];
__device__ float g_xm[(size_t)BB * MM * CC];
__device__ float g_qkv[(size_t)BB * MM * C3];
__device__ float g_attn[(size_t)BB * MM * CC];
__device__ float g_y[(size_t)BB * MM * CC];
__device__ float g_wqkv[CC * C3];
__device__ float g_wo[CC * CC];

// ---------------- 0. pre-round weights to tf32 ----------------
__global__ void roundcp_k(const float* __restrict__ s, float* __restrict__ d, int n) {
    int i = blockIdx.x * 256 + threadIdx.x;
    if (i < n) d[i] = tf32r(s[i]);
}

// ---------------- 1. normalized metric -> bf16 hi/lo (verified R11) ----------------
__global__ void metric_k(const float* __restrict__ x) {
    int row = blockIdx.x;
    int tid = threadIdx.x;                 // 256
    const float* p = x + (size_t)row * CC;
    float v0 = p[tid], v1 = p[tid + 256], v2 = p[tid + 512];
    float s = v0 * v0 + v1 * v1 + v2 * v2;
    __shared__ float red[256];
    red[tid] = s; __syncthreads();
    for (int o = 128; o > 0; o >>= 1) {
        if (tid < o) red[tid] += red[tid + o];
        __syncthreads();
    }
    float nrm = sqrtf(red[0]);
    size_t off = (size_t)row * CC;
#pragma unroll
    for (int q = 0; q < 3; q++) {
        float m = (q == 0 ? v0 : q == 1 ? v1 : v2) / nrm;
        __nv_bfloat16 h = __float2bfloat16_rn(m);
        __nv_bfloat16 lo = __float2bfloat16_rn(m - __bfloat162float(h));
        g_mhib[off + tid + q * 256] = h;
        g_mlob[off + tid + q * 256] = lo;
    }
}

// ---------------- 2. matching via 3xBF16 k16 MMA, 32-k chunks (24 iters) ----------------
// tile: 128 rows x 32 bf16 (64B payload), row stride 80B (5 units, coprime 8 -> conflict-free)
#define MT_TILE 10240
#define MT_SMEM (8 * MT_TILE)
__global__ __launch_bounds__(256, 2) void match_mma_k() {
    extern __shared__ float dsm[];
    unsigned sAH = smem_u32(dsm);
    unsigned sAL = sAH + 2 * MT_TILE;
    unsigned sBH = sAH + 4 * MT_TILE;
    unsigned sBL = sAH + 6 * MT_TILE;

    int dt = blockIdx.x, st = blockIdx.y, b = blockIdx.z;
    int tid = threadIdx.x;
    int w = tid >> 5, l = tid & 31;
    int wm = w & 3, wn = w >> 2;
    int lr = l >> 2, lc = l & 3;

    size_t bbase = (size_t)b * NN * CC;
    int fr = tid >> 1, fh = tid & 1;       // row, 16-elem half
    size_t aoff = bbase + (size_t)(2 * (st * 128 + fr)) * CC + fh * 16;
    size_t boff = bbase + (size_t)(2 * (dt * 128 + fr) + 1) * CC + fh * 16;
    const __nv_bfloat16* aH = g_mhib + aoff;
    const __nv_bfloat16* aL = g_mlob + aoff;
    const __nv_bfloat16* bH = g_mhib + boff;
    const __nv_bfloat16* bL = g_mlob + boff;
    unsigned dstoff = (unsigned)(fr * 80 + fh * 32);

    unsigned aAdr = (unsigned)((wm * 32 + (l & 15)) * 80 + ((l >> 4) & 1) * 16);
    unsigned bAdr = (unsigned)((wn * 64 + (l & 7) + ((l >> 4) & 1) * 8) * 80 + ((l >> 3) & 1) * 16);

    float acc[2][8][4] = {};

    auto issue = [&](int c, int buf) {
        unsigned d = dstoff + (unsigned)buf * MT_TILE;
        cp16(sAH + d, aH + c * 32);  cp16(sAH + d + 16, aH + c * 32 + 8);
        cp16(sAL + d, aL + c * 32);  cp16(sAL + d + 16, aL + c * 32 + 8);
        cp16(sBH + d, bH + c * 32);  cp16(sBH + d + 16, bH + c * 32 + 8);
        cp16(sBL + d, bL + c * 32);  cp16(sBL + d + 16, bL + c * 32 + 8);
    };

    issue(0, 0); cpcommit();
    int buf = 0;
    for (int c = 0; c < 24; c++) {
        cpwait0();
        __syncthreads();
        if (c + 1 < 24) { issue(c + 1, buf ^ 1); cpcommit(); }
        unsigned bo = (unsigned)buf * MT_TILE;
#pragma unroll
        for (int ks = 0; ks < 2; ks++) {       // two k16 slices per 32-chunk
            unsigned o = bo + ks * 32;
            unsigned ah[2][4], al[2][4];
            ldsm4(ah[0], sAH + o + aAdr);
            ldsm4(ah[1], sAH + o + aAdr + 16 * 80);
            ldsm4(al[0], sAL + o + aAdr);
            ldsm4(al[1], sAL + o + aAdr + 16 * 80);
            unsigned bh4[4][4];
#pragma unroll
            for (int ntp = 0; ntp < 4; ntp++) ldsm4(bh4[ntp], sBH + o + bAdr + ntp * 16 * 80);
            // hi*hi
#pragma unroll
            for (int ntp = 0; ntp < 4; ntp++) {
                mma16bf(acc[0][2 * ntp],     ah[0], bh4[ntp]);
                mma16bf(acc[1][2 * ntp],     ah[1], bh4[ntp]);
                mma16bf(acc[0][2 * ntp + 1], ah[0], bh4[ntp] + 2);
                mma16bf(acc[1][2 * ntp + 1], ah[1], bh4[ntp] + 2);
            }
            // lo*hi
#pragma unroll
            for (int ntp = 0; ntp < 4; ntp++) {
                mma16bf(acc[0][2 * ntp],     al[0], bh4[ntp]);
                mma16bf(acc[1][2 * ntp],     al[1], bh4[ntp]);
                mma16bf(acc[0][2 * ntp + 1], al[0], bh4[ntp] + 2);
                mma16bf(acc[1][2 * ntp + 1], al[1], bh4[ntp] + 2);
            }
            // hi*lo
#pragma unroll
            for (int ntp = 0; ntp < 4; ntp++) {
                unsigned bl4[4];
                ldsm4(bl4, sBL + o + bAdr + ntp * 16 * 80);
                mma16bf(acc[0][2 * ntp],     ah[0], bl4);
                mma16bf(acc[1][2 * ntp],     ah[1], bl4);
                mma16bf(acc[0][2 * ntp + 1], ah[0], bl4 + 2);
                mma16bf(acc[1][2 * ntp + 1], ah[1], bl4 + 2);
            }
        }
        buf ^= 1;
    }
    // fragment argmax epilogue (verified R8-R11)
    float* spm = dsm;
    int*   spi = (int*)(dsm + 256);
    __syncthreads();
#pragma unroll
    for (int mt = 0; mt < 2; mt++) {
        float bv0 = -INFINITY, bv1 = -INFINITY;
        int bi0 = 0, bi1 = 0;
#pragma unroll
        for (int nt = 0; nt < 8; nt++) {
            int cb = dt * 128 + wn * 64 + nt * 8 + 2 * lc;
            if (acc[mt][nt][0] > bv0) { bv0 = acc[mt][nt][0]; bi0 = cb; }
            if (acc[mt][nt][1] > bv0) { bv0 = acc[mt][nt][1]; bi0 = cb + 1; }
            if (acc[mt][nt][2] > bv1) { bv1 = acc[mt][nt][2]; bi1 = cb; }
            if (acc[mt][nt][3] > bv1) { bv1 = acc[mt][nt][3]; bi1 = cb + 1; }
        }
#pragma unroll
        for (int off = 1; off <= 2; off <<= 1) {
            float ov = __shfl_xor_sync(0xffffffffu, bv0, off);
            int   oi = __shfl_xor_sync(0xffffffffu, bi0, off);
            if (ov > bv0 || (ov == bv0 && oi < bi0)) { bv0 = ov; bi0 = oi; }
            ov = __shfl_xor_sync(0xffffffffu, bv1, off);
            oi = __shfl_xor_sync(0xffffffffu, bi1, off);
            if (ov > bv1 || (ov == bv1 && oi < bi1)) { bv1 = ov; bi1 = oi; }
        }
        if (lc == 0) {
            int r0 = wm * 32 + mt * 16 + lr;
            spm[wn * 128 + r0] = bv0;  spi[wn * 128 + r0] = bi0;
            spm[wn * 128 + r0 + 8] = bv1; spi[wn * 128 + r0 + 8] = bi1;
        }
    }
    __syncthreads();
    if (tid < 128) {
        float v0 = spm[tid], v1 = spm[128 + tid];
        int   i0 = spi[tid], i1 = spi[128 + tid];
        if (v1 > v0) { v0 = v1; i0 = i1; }
        g_pmax[(b * 8 + dt) * NSRC + st * 128 + tid] = v0;
        g_pidx[(b * 8 + dt) * NSRC + st * 128 + tid] = i0;
    }
}

// ---------------- 3. top-k (verified) ----------------
__global__ void topk_k() {
    __shared__ unsigned long long key[1024];
    __shared__ int nidx[1024];
    __shared__ int mrg[1024];
    __shared__ int scn[1024];
    int b = blockIdx.x, tid = threadIdx.x;   // 1024

    float bv = g_pmax[(b * 8) * NSRC + tid];
    int   bi = g_pidx[(b * 8) * NSRC + tid];
#pragma unroll
    for (int dt = 1; dt < 8; dt++) {
        float v = g_pmax[(b * 8 + dt) * NSRC + tid];
        if (v > bv) { bv = v; bi = g_pidx[(b * 8 + dt) * NSRC + tid]; }
    }
    nidx[tid] = bi;
    {
        unsigned u = __float_as_uint(bv);
        u = (u & 0x80000000u) ? ~u : (u | 0x80000000u);
        key[tid] = ((unsigned long long)(~u) << 32) | (unsigned)tid;
    }
    mrg[tid] = 0;
    g_lhead[b * NSRC + tid] = -1;
    __syncthreads();
    for (int k = 2; k <= 1024; k <<= 1)
        for (int j = k >> 1; j > 0; j >>= 1) {
            int p = tid ^ j;
            if (p > tid) {
                bool up = ((tid & k) == 0);
                unsigned long long a = key[tid], c2 = key[p];
                if ((a > c2) == up) { key[tid] = c2; key[p] = a; }
            }
            __syncthreads();
        }
    if (tid < 512) {
        int s = (int)(key[tid] & 0xffffffffu);
        g_srcidx[b * RR + tid] = s;
        mrg[s] = 1;
        int d = nidx[s];
        g_lnext[b * RR + tid] = atomicExch(&g_lhead[b * NSRC + d], tid);
    }
    __syncthreads();
    int um = mrg[tid] ? 0 : 1;
    scn[tid] = um; __syncthreads();
    for (int off = 1; off < 1024; off <<= 1) {
        int v = scn[tid];
        int v2 = (tid >= off) ? scn[tid - off] : 0;
        __syncthreads();
        scn[tid] = v + v2; __syncthreads();
    }
    int rnk = scn[tid] - um;
    if (um) { g_unmidx[b * RR + rnk] = tid; g_gather[b * NSRC + tid] = NDST + rnk; }
    else    { g_gather[b * NSRC + tid] = nidx[tid]; }
}

// ---------------- 4. fused merge build (emits tf32-rounded xm) ----------------
__global__ void buildall_k(const float* __restrict__ x) {
    int row = blockIdx.x;
    int b = row / MM, j = row - b * MM;
    int t = threadIdx.x;                    // 192
    float* dst = g_xm + (size_t)row * CC;
    if (j >= NDST) {
        int s = g_unmidx[b * RR + (j - NDST)];
        const float* src = x + ((size_t)b * NN + 2 * s) * CC;
        float4 v = *(const float4*)&src[t * 4];
        *(float4*)&dst[t * 4] =
            make_float4(tf32r(v.x), tf32r(v.y), tf32r(v.z), tf32r(v.w));
        return;
    }
    const float* dsrc = x + ((size_t)b * NN + 2 * j + 1) * CC;
    float4 v = *(const float4*)&dsrc[t * 4];
    float cntf = 1.f;
    int it = g_lhead[b * NSRC + j];
    while (it >= 0) {
        int s = g_srcidx[b * RR + it];
        float4 sv = *(const float4*)&x[((size_t)b * NN + 2 * s) * CC + t * 4];
        v.x += sv.x; v.y += sv.y; v.z += sv.z; v.w += sv.w;
        cntf += 1.f;
        it = g_lnext[b * RR + it];
    }
    float inv = 1.f / cntf;
    *(float4*)&dst[t * 4] =
        make_float4(tf32r(v.x * inv), tf32r(v.y * inv), tf32r(v.z * inv), tf32r(v.w * inv));
}

// ---------------- 5. tf32 GEMM, 32-k chunks (24 iters), dynamic smem ----------------
// smem row stride 36 floats (144B = 9 units, 9 ≡ 1 mod 8 -> ldsm conflict-free)
#define GT_TILE 18432                     // 128*36*4 bytes
#define GT_SMEM (4 * GT_TILE)             // A[2] + B[2]
__global__ __launch_bounds__(256, 2) void gemm_tf32_k(
        const float* __restrict__ A, const float* __restrict__ Bm,
        const float* __restrict__ bias, float* __restrict__ Cm, int Nd, int Kd, int rnd) {
    extern __shared__ float gsm[];
    float* As = gsm;                      // [2][128*36]
    float* Bs = gsm + 2 * 128 * 36;       // [2][128*36]
    int tid = threadIdx.x;
    int w = tid >> 5, l = tid & 31;
    int wm = w & 3, wn = w >> 2;
    int lr = l >> 2, lc = l & 3;
    int bm = blockIdx.y * 128, bn = blockIdx.x * 128;
    float acc[2][8][4] = {};

    int arow_a = (l & 7) + ((l >> 3) & 1) * 8;
    int acol_a = ((l >> 4) & 1) * 4;
    int arow_b = (l & 7) + ((l >> 4) & 1) * 8;
    int acol_b = ((l >> 3) & 1) * 4;
    unsigned aBase = smem_u32(As) + (unsigned)(((wm * 32 + arow_a) * 36 + acol_a) * 4);
    unsigned bBase = smem_u32(Bs) + (unsigned)(((wn * 64 + arow_b) * 36 + acol_b) * 4);

    int ar = tid >> 1, ah = tid & 1;      // A: row, 16-float half
    int bnn = tid & 127, bk = (tid >> 7) * 16;
    const float* Ap = A + (size_t)(bm + ar) * Kd + ah * 16;
    const float* Bp = Bm + bn + bnn;
    unsigned adst = smem_u32(As) + (unsigned)((ar * 36 + ah * 16) * 4);
    unsigned bdst = smem_u32(Bs) + (unsigned)((bnn * 36 + bk) * 4);

    auto issue = [&](int c, int buf) {
        unsigned off = (unsigned)buf * GT_TILE;
        const float* a = Ap + c * 32;
#pragma unroll
        for (int j = 0; j < 4; j++)
            cp16(adst + off + j * 16, a + j * 4);
#pragma unroll
        for (int i = 0; i < 16; i++)
            cp4(bdst + off + i * 4, Bp + (size_t)(c * 32 + bk + i) * Nd);
    };

    int nchunk = Kd >> 5;
    issue(0, 0); cpcommit();
    int buf = 0;
    for (int c = 0; c < nchunk; c++) {
        cpwait0();
        __syncthreads();
        if (c + 1 < nchunk) { issue(c + 1, buf ^ 1); cpcommit(); }
        unsigned bo = (unsigned)buf * GT_TILE;
#pragma unroll
        for (int ks = 0; ks < 4; ks++) {
            unsigned a0[4], a1[4];
            ldsm4(a0, aBase + bo + ks * 32);
            ldsm4(a1, aBase + bo + 16 * 144 + ks * 32);
#pragma unroll
            for (int ntp = 0; ntp < 4; ntp++) {
                unsigned bq[4];
                ldsm4(bq, bBase + bo + ntp * 16 * 144 + ks * 32);
                mma8(acc[0][2 * ntp],     a0, bq);
                mma8(acc[1][2 * ntp],     a1, bq);
                mma8(acc[0][2 * ntp + 1], a0, bq + 2);
                mma8(acc[1][2 * ntp + 1], a1, bq + 2);
            }
        }
        buf ^= 1;
    }
#pragma unroll
    for (int mt = 0; mt < 2; mt++) {
        int r0 = bm + wm * 32 + mt * 16 + lr;
#pragma unroll
        for (int nt = 0; nt < 8; nt++) {
            int c = bn + wn * 64 + nt * 8 + 2 * lc;
            float b0 = bias[c], b1 = bias[c + 1];
            float o0 = acc[mt][nt][0] + b0, o1 = acc[mt][nt][1] + b1;
            float o2 = acc[mt][nt][2] + b0, o3 = acc[mt][nt][3] + b1;
            if (rnd) { o0 = tf32r(o0); o1 = tf32r(o1); o2 = tf32r(o2); o3 = tf32r(o3); }
            *(float2*)&Cm[(size_t)r0 * Nd + c] = make_float2(o0, o1);
            *(float2*)&Cm[(size_t)(r0 + 8) * Nd + c] = make_float2(o2, o3);
        }
    }
}

// ---------------- 6. flash attention (R9-verified, byte-identical) ----------------
__global__ __launch_bounds__(256, 2) void flash_tf32_k(
        const float* __restrict__ qkv, float* __restrict__ o) {
    extern __shared__ float sm[];
    float* Qs = sm;                     // [128][68]
    float* Ks = sm + 8704;              // [2][64][68]
    float* Vs = sm + 8704 + 8704;       // [2][64][68], V^T slot-permuted cols

    int qt = blockIdx.x, bh = blockIdx.y;
    int b = bh / HH, h = bh % HH;
    const float* base = qkv + (size_t)b * MM * C3 + h * 64;
    int tid = threadIdx.x;
    int w = tid >> 5, l = tid & 31;
    int lr = l >> 2, lc = l & 3;
    int mr0 = w * 16 + lr;

    int arow_a = (l & 7) + ((l >> 3) & 1) * 8;
    int acol_a = ((l >> 4) & 1) * 4;
    int arow_b = (l & 7) + ((l >> 4) & 1) * 8;
    int acol_b = ((l >> 3) & 1) * 4;
    unsigned qB  = smem_u32(Qs) + (unsigned)(((w * 16 + arow_a) * 68 + acol_a) * 4);
    unsigned kB0 = smem_u32(Ks) + (unsigned)((arow_b * 68 + acol_b) * 4);
    unsigned vB0 = smem_u32(Vs) + (unsigned)((arow_b * 68 + acol_b) * 4);

    {   // Q fill: pre-rounded tf32; *0.125 exact
        int r = tid >> 1, hf = (tid & 1) * 32;
        const float* qp = base + (size_t)(qt * 128 + r) * C3 + hf;
#pragma unroll
        for (int i = 0; i < 8; i++) {
            float4 v = *(const float4*)(qp + i * 4);
            *(float4*)&Qs[r * 68 + hf + i * 4] =
                make_float4(v.x * 0.125f, v.y * 0.125f, v.z * 0.125f, v.w * 0.125f);
        }
    }
    int kr = tid >> 2, kq = (tid & 3) * 16;
    unsigned kdst = smem_u32(Ks) + (unsigned)((kr * 68 + kq) * 4);
    const float* kgp = base + CC + (size_t)kr * C3 + kq;
    int vd = tid & 63, vcb = (tid >> 6) * 16;
    const float* vgp = base + 2 * CC + (size_t)vcb * C3 + vd;
    float vr[16];

#pragma unroll
    for (int i = 0; i < 16; i++) vr[i] = vgp[(size_t)i * C3];
#pragma unroll
    for (int j = 0; j < 4; j++) cp16(kdst + j * 16, kgp + j * 4);
    cpcommit();

    float om[8][4] = {};
    float m0 = -INFINITY, m1 = -INFINITY, l0 = 0.f, l1 = 0.f;

    for (int kt = 0; kt < 24; kt++) {
        int buf = kt & 1;
        {
            float* Vw = Vs + buf * 4352;
#pragma unroll
            for (int i = 0; i < 16; i++) {
                int c = vcb + i;
                int phys = (c & ~7) | (((c & 7) >> 1) + ((c & 1) << 2));
                Vw[vd * 68 + phys] = vr[i];
            }
        }
        cpwait0();
        __syncthreads();
        if (kt + 1 < 24) {
            unsigned d2 = kdst + (buf ^ 1) * 17408u;
            const float* g = kgp + (size_t)(kt + 1) * 64 * C3;
#pragma unroll
            for (int j = 0; j < 4; j++) cp16(d2 + j * 16, g + j * 4);
            cpcommit();
        }
        unsigned kB = kB0 + buf * 17408u;
        float s[8][4] = {};
#pragma unroll
        for (int ks = 0; ks < 8; ks++) {
            unsigned af[4];
            ldsm4(af, qB + ks * 32);
#pragma unroll
            for (int ntp = 0; ntp < 4; ntp++) {
                unsigned bq[4];
                ldsm4(bq, kB + ntp * 16 * 272 + ks * 32);
                mma8(s[2 * ntp],     af, bq);
                mma8(s[2 * ntp + 1], af, bq + 2);
            }
        }
        if (kt + 1 < 24) {
            const float* g = vgp + (size_t)(kt + 1) * 64 * C3;
#pragma unroll
            for (int i = 0; i < 16; i++) vr[i] = g[(size_t)i * C3];
        }
        float mx0 = -INFINITY, mx1 = -INFINITY;
#pragma unroll
        for (int nt = 0; nt < 8; nt++) {
            mx0 = fmaxf(mx0, fmaxf(s[nt][0], s[nt][1]));
            mx1 = fmaxf(mx1, fmaxf(s[nt][2], s[nt][3]));
        }
        mx0 = fmaxf(mx0, __shfl_xor_sync(0xffffffffu, mx0, 1));
        mx0 = fmaxf(mx0, __shfl_xor_sync(0xffffffffu, mx0, 2));
        mx1 = fmaxf(mx1, __shfl_xor_sync(0xffffffffu, mx1, 1));
        mx1 = fmaxf(mx1, __shfl_xor_sync(0xffffffffu, mx1, 2));
        float mn0 = fmaxf(m0, mx0), mn1 = fmaxf(m1, mx1);
        float al0 = __expf(m0 - mn0), al1 = __expf(m1 - mn1);
        m0 = mn0; m1 = mn1;
        float rs0 = 0.f, rs1 = 0.f;
#pragma unroll
        for (int nt = 0; nt < 8; nt++) {
            float p0 = __expf(s[nt][0] - mn0), p1 = __expf(s[nt][1] - mn0);
            float p2 = __expf(s[nt][2] - mn1), p3 = __expf(s[nt][3] - mn1);
            rs0 += p0 + p1; rs1 += p2 + p3;
            s[nt][0] = tf32r(p0); s[nt][1] = tf32r(p1);
            s[nt][2] = tf32r(p2); s[nt][3] = tf32r(p3);
        }
        rs0 += __shfl_xor_sync(0xffffffffu, rs0, 1);
        rs0 += __shfl_xor_sync(0xffffffffu, rs0, 2);
        rs1 += __shfl_xor_sync(0xffffffffu, rs1, 1);
        rs1 += __shfl_xor_sync(0xffffffffu, rs1, 2);
        l0 = l0 * al0 + rs0; l1 = l1 * al1 + rs1;
#pragma unroll
        for (int nt = 0; nt < 8; nt++) {
            om[nt][0] *= al0; om[nt][1] *= al0;
            om[nt][2] *= al1; om[nt][3] *= al1;
        }
        unsigned vB = vB0 + buf * 17408u;
#pragma unroll
        for (int ks = 0; ks < 8; ks++) {
            unsigned af[4] = { U(s[ks][0]), U(s[ks][2]), U(s[ks][1]), U(s[ks][3]) };
#pragma unroll
            for (int ntp = 0; ntp < 4; ntp++) {
                unsigned bq[4];
                ldsm4(bq, vB + ntp * 16 * 272 + ks * 32);
                mma8(om[2 * ntp],     af, bq);
                mma8(om[2 * ntp + 1], af, bq + 2);
            }
        }
    }
    float i0 = 1.f / l0, i1 = 1.f / l1;
    size_t row0 = (size_t)b * MM + qt * 128 + mr0;
#pragma unroll
    for (int nt = 0; nt < 8; nt++) {
        int c = h * 64 + nt * 8 + 2 * lc;
        *(float2*)&o[row0 * CC + c] =
            make_float2(tf32r(om[nt][0] * i0), tf32r(om[nt][1] * i0));
        *(float2*)&o[(row0 + 8) * CC + c] =
            make_float2(tf32r(om[nt][2] * i1), tf32r(om[nt][3] * i1));
    }
}

// ---------------- 7. unmerge ----------------
__global__ void unmerge_k(float* __restrict__ out) {
    int row = blockIdx.x;
    int b = row >> 11;
    int n = row & 2047;
    int yrow = (n & 1) ? (n >> 1) : g_gather[b * NSRC + (n >> 1)];
    const float* src = g_y + ((size_t)b * MM + yrow) * CC;
    float* dst = out + (size_t)row * CC;
    int t = threadIdx.x;                  // 192
    *(float4*)&dst[t * 4] = *(const float4*)&src[t * 4];
}

// ---------------- launcher ----------------
extern "C" void kernel_launch(void* const* d_in, const int* in_sizes, int n_in,
                              void* d_out, int out_size) {
    const float* x    = (const float*)d_in[0];
    const float* Wqkv = (const float*)d_in[1];
    const float* bqkv = (const float*)d_in[2];
    const float* Wo   = (const float*)d_in[3];
    const float* bo   = (const float*)d_in[4];
    float* out = (float*)d_out;

    float *xm, *qkvb, *attnb, *yb, *wq, *wo;
    cudaGetSymbolAddress((void**)&xm, g_xm);
    cudaGetSymbolAddress((void**)&qkvb, g_qkv);
    cudaGetSymbolAddress((void**)&attnb, g_attn);
    cudaGetSymbolAddress((void**)&yb, g_y);
    cudaGetSymbolAddress((void**)&wq, g_wqkv);
    cudaGetSymbolAddress((void**)&wo, g_wo);

    cudaFuncSetAttribute(flash_tf32_k, cudaFuncAttributeMaxDynamicSharedMemorySize, 104448);
    cudaFuncSetAttribute(match_mma_k, cudaFuncAttributeMaxDynamicSharedMemorySize, MT_SMEM);
    cudaFuncSetAttribute(gemm_tf32_k, cudaFuncAttributeMaxDynamicSharedMemorySize, GT_SMEM);

    roundcp_k<<<(CC * C3 + 255) / 256, 256>>>(Wqkv, wq, CC * C3);
    roundcp_k<<<(CC * CC + 255) / 256, 256>>>(Wo, wo, CC * CC);
    metric_k<<<BB * NN, 256>>>(x);
    match_mma_k<<<dim3(8, 8, 8), 256, MT_SMEM>>>();
    topk_k<<<BB, 1024>>>();
    buildall_k<<<BB * MM, 192>>>(x);
    gemm_tf32_k<<<dim3(C3 / 128, (BB * MM) / 128), 256, GT_SMEM>>>(xm, wq, bqkv, qkvb, C3, CC, 1);
    flash_tf32_k<<<dim3(MM / 128, BB * HH), 256, 104448>>>(qkvb, attnb);
    gemm_tf32_k<<<dim3(CC / 128, (BB * MM) / 128), 256, GT_SMEM>>>(attnb, wo, bo, yb, CC, CC, 0);
    unmerge_k<<<BB * NN, 192>>>(out);
}

// round 14
// speedup vs baseline: 1.7283x; 1.7283x over previous
#include <cuda_runtime.h>
#include <cuda_bf16.h>
#include <cuda_fp16.h>
#include <math.h>

#define BB 8
#define NN 2048
#define CC 768
#define HH 12
#define MM 1536
#define RR 512
#define NSRC 1024
#define NDST 1024
#define C3 2304

__device__ __forceinline__ void mma16bf(float c[4], const unsigned a[4], const unsigned b[2]) {
    asm volatile("mma.sync.aligned.m16n8k16.row.col.f32.bf16.bf16.f32 "
        "{%0,%1,%2,%3}, {%4,%5,%6,%7}, {%8,%9}, {%0,%1,%2,%3};"
        : "+f"(c[0]), "+f"(c[1]), "+f"(c[2]), "+f"(c[3])
        : "r"(a[0]), "r"(a[1]), "r"(a[2]), "r"(a[3]), "r"(b[0]), "r"(b[1]));
}
__device__ __forceinline__ void mma16f(float c[4], const unsigned a[4], const unsigned b[2]) {
    asm volatile("mma.sync.aligned.m16n8k16.row.col.f32.f16.f16.f32 "
        "{%0,%1,%2,%3}, {%4,%5,%6,%7}, {%8,%9}, {%0,%1,%2,%3};"
        : "+f"(c[0]), "+f"(c[1]), "+f"(c[2]), "+f"(c[3])
        : "r"(a[0]), "r"(a[1]), "r"(a[2]), "r"(a[3]), "r"(b[0]), "r"(b[1]));
}
__device__ __forceinline__ void ldsm4(unsigned r[4], unsigned addr) {
    asm volatile("ldmatrix.sync.aligned.m8n8.x4.shared.b16 {%0,%1,%2,%3}, [%4];"
        : "=r"(r[0]), "=r"(r[1]), "=r"(r[2]), "=r"(r[3]) : "r"(addr));
}
__device__ __forceinline__ void ldsm4t(unsigned r[4], unsigned addr) {
    asm volatile("ldmatrix.sync.aligned.m8n8.x4.trans.shared.b16 {%0,%1,%2,%3}, [%4];"
        : "=r"(r[0]), "=r"(r[1]), "=r"(r[2]), "=r"(r[3]) : "r"(addr));
}
__device__ __forceinline__ unsigned smem_u32(const void* p) {
    return (unsigned)__cvta_generic_to_shared(p);
}
__device__ __forceinline__ void cp16(unsigned d, const void* s) {
    asm volatile("cp.async.cg.shared.global [%0], [%1], 16;" :: "r"(d), "l"(s));
}
__device__ __forceinline__ void cpcommit() { asm volatile("cp.async.commit_group;"); }
__device__ __forceinline__ void cpwait0()  { asm volatile("cp.async.wait_group 0;"); }
__device__ __forceinline__ unsigned packh2(float lo, float hi) {
    __half2 h = __floats2half2_rn(lo, hi);
    return *reinterpret_cast<unsigned*>(&h);
}

// ---------------- scratch ----------------
__device__ __nv_bfloat16 g_mhib[(size_t)BB * NN * CC];
__device__ __nv_bfloat16 g_mlob[(size_t)BB * NN * CC];
__device__ float g_pmax[BB * 8 * NSRC];
__device__ int   g_pidx[BB * 8 * NSRC];
__device__ int   g_srcidx[BB * RR];
__device__ int   g_unmidx[BB * RR];
__device__ int   g_gather[BB * NSRC];
__device__ int   g_lhead[BB * NSRC];
__device__ int   g_lnext[BB * RR];
__device__ __half g_xm[(size_t)BB * MM * CC];
__device__ __half g_qkv[(size_t)BB * MM * C3];
__device__ __half g_attn[(size_t)BB * MM * CC];
__device__ float  g_y[(size_t)BB * MM * CC];
__device__ __half g_wqkv[CC * C3];
__device__ __half g_wo[CC * CC];

// ---------------- 0. pre-round weights to fp16 ----------------
__global__ void roundcph_k(const float* __restrict__ s, __half* __restrict__ d, int n) {
    int i = blockIdx.x * 256 + threadIdx.x;
    if (i < n) d[i] = __float2half_rn(s[i]);
}

// ---------------- 1. normalized metric -> bf16 hi/lo (verified R11) ----------------
__global__ void metric_k(const float* __restrict__ x) {
    int row = blockIdx.x;
    int tid = threadIdx.x;                 // 256
    const float* p = x + (size_t)row * CC;
    float v0 = p[tid], v1 = p[tid + 256], v2 = p[tid + 512];
    float s = v0 * v0 + v1 * v1 + v2 * v2;
    __shared__ float red[256];
    red[tid] = s; __syncthreads();
    for (int o = 128; o > 0; o >>= 1) {
        if (tid < o) red[tid] += red[tid + o];
        __syncthreads();
    }
    float nrm = sqrtf(red[0]);
    size_t off = (size_t)row * CC;
#pragma unroll
    for (int q = 0; q < 3; q++) {
        float m = (q == 0 ? v0 : q == 1 ? v1 : v2) / nrm;
        __nv_bfloat16 h = __float2bfloat16_rn(m);
        __nv_bfloat16 lo = __float2bfloat16_rn(m - __bfloat162float(h));
        g_mhib[off + tid + q * 256] = h;
        g_mlob[off + tid + q * 256] = lo;
    }
}

// ---------------- 2. matching via 3xBF16 k16 MMA (R11-verified, verbatim) ----------------
#define MT_TILE 6144
__global__ __launch_bounds__(256, 2) void match_mma_k() {
    extern __shared__ float dsm[];
    char* smb = (char*)dsm;
    unsigned sAH = smem_u32(smb);
    unsigned sAL = sAH + 2 * MT_TILE;
    unsigned sBH = sAH + 4 * MT_TILE;
    unsigned sBL = sAH + 6 * MT_TILE;

    int dt = blockIdx.x, st = blockIdx.y, b = blockIdx.z;
    int tid = threadIdx.x;
    int w = tid >> 5, l = tid & 31;
    int wm = w & 3, wn = w >> 2;
    int lr = l >> 2, lc = l & 3;

    size_t bbase = (size_t)b * NN * CC;
    int r = tid >> 1, half = tid & 1;
    size_t aoff = bbase + (size_t)(2 * (st * 128 + r)) * CC + half * 8;
    size_t boff = bbase + (size_t)(2 * (dt * 128 + r) + 1) * CC + half * 8;
    const __nv_bfloat16* aH = g_mhib + aoff;
    const __nv_bfloat16* aL = g_mlob + aoff;
    const __nv_bfloat16* bH = g_mhib + boff;
    const __nv_bfloat16* bL = g_mlob + boff;
    unsigned dstoff = (unsigned)(r * 48 + half * 16);

    unsigned aAdr = (unsigned)((wm * 32 + (l & 15)) * 48 + ((l >> 4) & 1) * 16);
    unsigned bAdr = (unsigned)((wn * 64 + (l & 7) + ((l >> 4) & 1) * 8) * 48 + ((l >> 3) & 1) * 16);

    float acc[2][8][4] = {};

    auto issue = [&](int c, int buf) {
        unsigned d = dstoff + (unsigned)buf * MT_TILE;
        cp16(sAH + d, aH + c * 16);
        cp16(sAL + d, aL + c * 16);
        cp16(sBH + d, bH + c * 16);
        cp16(sBL + d, bL + c * 16);
    };

    issue(0, 0); cpcommit();
    int buf = 0;
    for (int c = 0; c < 48; c++) {
        cpwait0();
        __syncthreads();
        if (c + 1 < 48) { issue(c + 1, buf ^ 1); cpcommit(); }
        unsigned bo = (unsigned)buf * MT_TILE;
        unsigned ah[2][4], al[2][4];
        ldsm4(ah[0], sAH + bo + aAdr);
        ldsm4(ah[1], sAH + bo + aAdr + 16 * 48);
        ldsm4(al[0], sAL + bo + aAdr);
        ldsm4(al[1], sAL + bo + aAdr + 16 * 48);
        unsigned bh4[4][4];
#pragma unroll
        for (int ntp = 0; ntp < 4; ntp++) ldsm4(bh4[ntp], sBH + bo + bAdr + ntp * 16 * 48);
#pragma unroll
        for (int ntp = 0; ntp < 4; ntp++) {      // hi*hi
            mma16bf(acc[0][2 * ntp],     ah[0], bh4[ntp]);
            mma16bf(acc[1][2 * ntp],     ah[1], bh4[ntp]);
            mma16bf(acc[0][2 * ntp + 1], ah[0], bh4[ntp] + 2);
            mma16bf(acc[1][2 * ntp + 1], ah[1], bh4[ntp] + 2);
        }
#pragma unroll
        for (int ntp = 0; ntp < 4; ntp++) {      // lo*hi
            mma16bf(acc[0][2 * ntp],     al[0], bh4[ntp]);
            mma16bf(acc[1][2 * ntp],     al[1], bh4[ntp]);
            mma16bf(acc[0][2 * ntp + 1], al[0], bh4[ntp] + 2);
            mma16bf(acc[1][2 * ntp + 1], al[1], bh4[ntp] + 2);
        }
#pragma unroll
        for (int ntp = 0; ntp < 4; ntp++) {      // hi*lo
            unsigned bl4[4];
            ldsm4(bl4, sBL + bo + bAdr + ntp * 16 * 48);
            mma16bf(acc[0][2 * ntp],     ah[0], bl4);
            mma16bf(acc[1][2 * ntp],     ah[1], bl4);
            mma16bf(acc[0][2 * ntp + 1], ah[0], bl4 + 2);
            mma16bf(acc[1][2 * ntp + 1], ah[1], bl4 + 2);
        }
        buf ^= 1;
    }
    float* spm = dsm;
    int*   spi = (int*)(dsm + 256);
    __syncthreads();
#pragma unroll
    for (int mt = 0; mt < 2; mt++) {
        float bv0 = -INFINITY, bv1 = -INFINITY;
        int bi0 = 0, bi1 = 0;
#pragma unroll
        for (int nt = 0; nt < 8; nt++) {
            int cb = dt * 128 + wn * 64 + nt * 8 + 2 * lc;
            if (acc[mt][nt][0] > bv0) { bv0 = acc[mt][nt][0]; bi0 = cb; }
            if (acc[mt][nt][1] > bv0) { bv0 = acc[mt][nt][1]; bi0 = cb + 1; }
            if (acc[mt][nt][2] > bv1) { bv1 = acc[mt][nt][2]; bi1 = cb; }
            if (acc[mt][nt][3] > bv1) { bv1 = acc[mt][nt][3]; bi1 = cb + 1; }
        }
#pragma unroll
        for (int off = 1; off <= 2; off <<= 1) {
            float ov = __shfl_xor_sync(0xffffffffu, bv0, off);
            int   oi = __shfl_xor_sync(0xffffffffu, bi0, off);
            if (ov > bv0 || (ov == bv0 && oi < bi0)) { bv0 = ov; bi0 = oi; }
            ov = __shfl_xor_sync(0xffffffffu, bv1, off);
            oi = __shfl_xor_sync(0xffffffffu, bi1, off);
            if (ov > bv1 || (ov == bv1 && oi < bi1)) { bv1 = ov; bi1 = oi; }
        }
        if (lc == 0) {
            int r0 = wm * 32 + mt * 16 + lr;
            spm[wn * 128 + r0] = bv0;  spi[wn * 128 + r0] = bi0;
            spm[wn * 128 + r0 + 8] = bv1; spi[wn * 128 + r0 + 8] = bi1;
        }
    }
    __syncthreads();
    if (tid < 128) {
        float v0 = spm[tid], v1 = spm[128 + tid];
        int   i0 = spi[tid], i1 = spi[128 + tid];
        if (v1 > v0) { v0 = v1; i0 = i1; }
        g_pmax[(b * 8 + dt) * NSRC + st * 128 + tid] = v0;
        g_pidx[(b * 8 + dt) * NSRC + st * 128 + tid] = i0;
    }
}

// ---------------- 3. top-k (verified) ----------------
__global__ void topk_k() {
    __shared__ unsigned long long key[1024];
    __shared__ int nidx[1024];
    __shared__ int mrg[1024];
    __shared__ int scn[1024];
    int b = blockIdx.x, tid = threadIdx.x;   // 1024

    float bv = g_pmax[(b * 8) * NSRC + tid];
    int   bi = g_pidx[(b * 8) * NSRC + tid];
#pragma unroll
    for (int dt = 1; dt < 8; dt++) {
        float v = g_pmax[(b * 8 + dt) * NSRC + tid];
        if (v > bv) { bv = v; bi = g_pidx[(b * 8 + dt) * NSRC + tid]; }
    }
    nidx[tid] = bi;
    {
        unsigned u = __float_as_uint(bv);
        u = (u & 0x80000000u) ? ~u : (u | 0x80000000u);
        key[tid] = ((unsigned long long)(~u) << 32) | (unsigned)tid;
    }
    mrg[tid] = 0;
    g_lhead[b * NSRC + tid] = -1;
    __syncthreads();
    for (int k = 2; k <= 1024; k <<= 1)
        for (int j = k >> 1; j > 0; j >>= 1) {
            int p = tid ^ j;
            if (p > tid) {
                bool up = ((tid & k) == 0);
                unsigned long long a = key[tid], c2 = key[p];
                if ((a > c2) == up) { key[tid] = c2; key[p] = a; }
            }
            __syncthreads();
        }
    if (tid < 512) {
        int s = (int)(key[tid] & 0xffffffffu);
        g_srcidx[b * RR + tid] = s;
        mrg[s] = 1;
        int d = nidx[s];
        g_lnext[b * RR + tid] = atomicExch(&g_lhead[b * NSRC + d], tid);
    }
    __syncthreads();
    int um = mrg[tid] ? 0 : 1;
    scn[tid] = um; __syncthreads();
    for (int off = 1; off < 1024; off <<= 1) {
        int v = scn[tid];
        int v2 = (tid >= off) ? scn[tid - off] : 0;
        __syncthreads();
        scn[tid] = v + v2; __syncthreads();
    }
    int rnk = scn[tid] - um;
    if (um) { g_unmidx[b * RR + rnk] = tid; g_gather[b * NSRC + tid] = NDST + rnk; }
    else    { g_gather[b * NSRC + tid] = nidx[tid]; }
}

// ---------------- 4. fused merge build (emits fp16 xm) ----------------
__global__ void buildall_k(const float* __restrict__ x) {
    int row = blockIdx.x;
    int b = row / MM, j = row - b * MM;
    int t = threadIdx.x;                    // 192
    __half* dst = g_xm + (size_t)row * CC;
    if (j >= NDST) {
        int s = g_unmidx[b * RR + (j - NDST)];
        const float* src = x + ((size_t)b * NN + 2 * s) * CC;
        float4 v = *(const float4*)&src[t * 4];
        uint2 o = { packh2(v.x, v.y), packh2(v.z, v.w) };
        *(uint2*)&dst[t * 4] = o;
        return;
    }
    const float* dsrc = x + ((size_t)b * NN + 2 * j + 1) * CC;
    float4 v = *(const float4*)&dsrc[t * 4];
    float cntf = 1.f;
    int it = g_lhead[b * NSRC + j];
    while (it >= 0) {
        int s = g_srcidx[b * RR + it];
        float4 sv = *(const float4*)&x[((size_t)b * NN + 2 * s) * CC + t * 4];
        v.x += sv.x; v.y += sv.y; v.z += sv.z; v.w += sv.w;
        cntf += 1.f;
        it = g_lnext[b * RR + it];
    }
    float inv = 1.f / cntf;
    uint2 o = { packh2(v.x * inv, v.y * inv), packh2(v.z * inv, v.w * inv) };
    *(uint2*)&dst[t * 4] = o;
}

// ---------------- 5. fp16 GEMM k16: C = A*B + bias; out fp16 (outh=1) or fp32 ----------------
// A [m][k] fp16 rows 64B payload stride 80B; B [k][n] fp16 rows 256B payload stride 272B (trans ldsm)
__global__ __launch_bounds__(256, 2) void gemm_fp16_k(
        const __half* __restrict__ A, const __half* __restrict__ Bm,
        const float* __restrict__ bias, void* Cv, int Nd, int outh) {
    __shared__ __align__(16) char gsm[2 * 10240 + 2 * 8704];
    unsigned sA = smem_u32(gsm);
    unsigned sB = sA + 20480;
    int tid = threadIdx.x;
    int w = tid >> 5, l = tid & 31;
    int wm = w & 3, wn = w >> 2;
    int lr = l >> 2, lc = l & 3;
    int bm = blockIdx.y * 128, bn = blockIdx.x * 128;
    float acc[2][8][4] = {};

    int ar = tid >> 1, ah = tid & 1;
    const __half* Ap = A + (size_t)(bm + ar) * CC + ah * 16;
    unsigned adst = sA + (unsigned)(ar * 80 + ah * 32);
    int br = tid >> 3, bc = tid & 7;
    const __half* Bp = Bm + bn + bc * 16;
    unsigned bdst = sB + (unsigned)(br * 272 + bc * 32);

    unsigned aAdr = sA + (unsigned)((wm * 32 + (l & 15)) * 80 + ((l >> 4) & 1) * 16);
    unsigned bAdr = sB + (unsigned)(((l & 7) + ((l >> 3) & 1) * 8) * 272
                         + (wn * 64 + ((l >> 4) & 1) * 8) * 2);

    auto issue = [&](int c, int buf) {
        const __half* a = Ap + c * 32;
        cp16(adst + buf * 10240u, a);
        cp16(adst + buf * 10240u + 16, a + 8);
        const __half* bsrc = Bp + (size_t)(c * 32 + br) * Nd;
        cp16(bdst + buf * 8704u, bsrc);
        cp16(bdst + buf * 8704u + 16, bsrc + 8);
    };

    issue(0, 0); cpcommit();
    int buf = 0;
    for (int c = 0; c < 24; c++) {
        cpwait0();
        __syncthreads();
        if (c + 1 < 24) { issue(c + 1, buf ^ 1); cpcommit(); }
        unsigned ao = buf * 10240u, bo = buf * 8704u;
#pragma unroll
        for (int ks = 0; ks < 2; ks++) {
            unsigned a0[4], a1[4];
            ldsm4(a0, aAdr + ao + ks * 32);
            ldsm4(a1, aAdr + ao + 16 * 80 + ks * 32);
#pragma unroll
            for (int ntp = 0; ntp < 4; ntp++) {
                unsigned bq[4];
                ldsm4t(bq, bAdr + bo + ks * 16 * 272 + ntp * 32);
                mma16f(acc[0][2 * ntp],     a0, bq);
                mma16f(acc[1][2 * ntp],     a1, bq);
                mma16f(acc[0][2 * ntp + 1], a0, bq + 2);
                mma16f(acc[1][2 * ntp + 1], a1, bq + 2);
            }
        }
        buf ^= 1;
    }
#pragma unroll
    for (int mt = 0; mt < 2; mt++) {
        int r0 = bm + wm * 32 + mt * 16 + lr;
#pragma unroll
        for (int nt = 0; nt < 8; nt++) {
            int c = bn + wn * 64 + nt * 8 + 2 * lc;
            float b0 = bias[c], b1 = bias[c + 1];
            float o0 = acc[mt][nt][0] + b0, o1 = acc[mt][nt][1] + b1;
            float o2 = acc[mt][nt][2] + b0, o3 = acc[mt][nt][3] + b1;
            if (outh) {
                __half* C = (__half*)Cv;
                *(unsigned*)&C[(size_t)r0 * Nd + c] = packh2(o0, o1);
                *(unsigned*)&C[(size_t)(r0 + 8) * Nd + c] = packh2(o2, o3);
            } else {
                float* C = (float*)Cv;
                *(float2*)&C[(size_t)r0 * Nd + c] = make_float2(o0, o1);
                *(float2*)&C[(size_t)(r0 + 8) * Nd + c] = make_float2(o2, o3);
            }
        }
    }
}

// ---------------- 6. flash attention fp16 k16 (Q/K/V fp16, P fp16, fp32 softmax) ----------------
// tiles stride 144B, payload 128B (64 fp16). Q[128], K[2][64], V[2][64] (token-major, trans ldsm)
#define FL_SMEM (18432 + 2 * 9216 + 2 * 9216)
__global__ __launch_bounds__(256, 2) void flash_fp16_k(
        const __half* __restrict__ qkv, __half* __restrict__ o) {
    extern __shared__ char fsm[];
    unsigned sQ = smem_u32(fsm);
    unsigned sK = sQ + 18432;
    unsigned sV = sK + 2 * 9216;

    int qt = blockIdx.x, bh = blockIdx.y;
    int b = bh / HH, h = bh % HH;
    const __half* base = qkv + (size_t)b * MM * C3 + h * 64;
    int tid = threadIdx.x;
    int w = tid >> 5, l = tid & 31;
    int lr = l >> 2, lc = l & 3;
    int mr0 = w * 16 + lr;

    unsigned qAdr = sQ + (unsigned)((w * 16 + (l & 15)) * 144 + ((l >> 4) & 1) * 16);
    unsigned kAdr = sK + (unsigned)(((l & 7) + ((l >> 4) & 1) * 8) * 144 + ((l >> 3) & 1) * 16);
    unsigned vAdr = sV + (unsigned)(((l & 7) + ((l >> 3) & 1) * 8) * 144 + ((l >> 4) & 1) * 16);

    {   // Q fill with exact *0.125 scale
        int r = tid >> 1, hf = (tid & 1) * 32;
        const __half2* qp = (const __half2*)(base + (size_t)(qt * 128 + r) * C3 + hf);
        __half2* dq = (__half2*)(fsm + r * 144 + hf * 2);
        __half2 sc = __floats2half2_rn(0.125f, 0.125f);
#pragma unroll
        for (int i = 0; i < 16; i++) dq[i] = __hmul2(qp[i], sc);
    }
    int kr = tid >> 2, kq = (tid & 3) * 16;
    unsigned kdst = sK + (unsigned)(kr * 144 + (tid & 3) * 32);
    unsigned vdst = sV + (unsigned)(kr * 144 + (tid & 3) * 32);
    const __half* kgp = base + CC + (size_t)kr * C3 + kq;
    const __half* vgp = base + 2 * CC + (size_t)kr * C3 + kq;

    auto issue = [&](int kt, int buf) {
        const __half* ks = kgp + (size_t)kt * 64 * C3;
        const __half* vs = vgp + (size_t)kt * 64 * C3;
        cp16(kdst + buf * 9216u, ks);  cp16(kdst + buf * 9216u + 16, ks + 8);
        cp16(vdst + buf * 9216u, vs);  cp16(vdst + buf * 9216u + 16, vs + 8);
        cpcommit();
    };
    issue(0, 0);

    float om[8][4] = {};
    float m0 = -INFINITY, m1 = -INFINITY, l0 = 0.f, l1 = 0.f;

    for (int kt = 0; kt < 24; kt++) {
        int buf = kt & 1;
        cpwait0();
        __syncthreads();
        if (kt + 1 < 24) issue(kt + 1, buf ^ 1);
        // S = Q K^T  (Q pre-scaled)
        float s[8][4] = {};
#pragma unroll
        for (int ks = 0; ks < 4; ks++) {
            unsigned af[4];
            ldsm4(af, qAdr + ks * 32);
#pragma unroll
            for (int ntp = 0; ntp < 4; ntp++) {
                unsigned bq[4];
                ldsm4(bq, kAdr + buf * 9216u + ntp * 2304 + ks * 32);
                mma16f(s[2 * ntp],     af, bq);
                mma16f(s[2 * ntp + 1], af, bq + 2);
            }
        }
        // online softmax (fp32)
        float mx0 = -INFINITY, mx1 = -INFINITY;
#pragma unroll
        for (int nt = 0; nt < 8; nt++) {
            mx0 = fmaxf(mx0, fmaxf(s[nt][0], s[nt][1]));
            mx1 = fmaxf(mx1, fmaxf(s[nt][2], s[nt][3]));
        }
        mx0 = fmaxf(mx0, __shfl_xor_sync(0xffffffffu, mx0, 1));
        mx0 = fmaxf(mx0, __shfl_xor_sync(0xffffffffu, mx0, 2));
        mx1 = fmaxf(mx1, __shfl_xor_sync(0xffffffffu, mx1, 1));
        mx1 = fmaxf(mx1, __shfl_xor_sync(0xffffffffu, mx1, 2));
        float mn0 = fmaxf(m0, mx0), mn1 = fmaxf(m1, mx1);
        float al0 = __expf(m0 - mn0), al1 = __expf(m1 - mn1);
        m0 = mn0; m1 = mn1;
        float rs0 = 0.f, rs1 = 0.f;
#pragma unroll
        for (int nt = 0; nt < 8; nt++) {
            s[nt][0] = __expf(s[nt][0] - mn0); rs0 += s[nt][0];
            s[nt][1] = __expf(s[nt][1] - mn0); rs0 += s[nt][1];
            s[nt][2] = __expf(s[nt][2] - mn1); rs1 += s[nt][2];
            s[nt][3] = __expf(s[nt][3] - mn1); rs1 += s[nt][3];
        }
        rs0 += __shfl_xor_sync(0xffffffffu, rs0, 1);
        rs0 += __shfl_xor_sync(0xffffffffu, rs0, 2);
        rs1 += __shfl_xor_sync(0xffffffffu, rs1, 1);
        rs1 += __shfl_xor_sync(0xffffffffu, rs1, 2);
        l0 = l0 * al0 + rs0; l1 = l1 * al1 + rs1;
#pragma unroll
        for (int nt = 0; nt < 8; nt++) {
            om[nt][0] *= al0; om[nt][1] *= al0;
            om[nt][2] *= al1; om[nt][3] *= al1;
        }
        // O += P V (P packed to fp16 A-fragments; V via trans ldsm, token-major)
#pragma unroll
        for (int ks = 0; ks < 4; ks++) {
            unsigned af[4] = {
                packh2(s[2 * ks][0],     s[2 * ks][1]),
                packh2(s[2 * ks][2],     s[2 * ks][3]),
                packh2(s[2 * ks + 1][0], s[2 * ks + 1][1]),
                packh2(s[2 * ks + 1][2], s[2 * ks + 1][3])
            };
#pragma unroll
            for (int ntp = 0; ntp < 4; ntp++) {
                unsigned bq[4];
                ldsm4t(bq, vAdr + buf * 9216u + ks * 2304 + ntp * 32);
                mma16f(om[2 * ntp],     af, bq);
                mma16f(om[2 * ntp + 1], af, bq + 2);
            }
        }
    }
    float i0 = 1.f / l0, i1 = 1.f / l1;
    size_t row0 = (size_t)b * MM + qt * 128 + mr0;
#pragma unroll
    for (int nt = 0; nt < 8; nt++) {
        int c = h * 64 + nt * 8 + 2 * lc;
        *(unsigned*)&o[row0 * CC + c] = packh2(om[nt][0] * i0, om[nt][1] * i0);
        *(unsigned*)&o[(row0 + 8) * CC + c] = packh2(om[nt][2] * i1, om[nt][3] * i1);
    }
}

// ---------------- 7. unmerge ----------------
__global__ void unmerge_k(float* __restrict__ out) {
    int row = blockIdx.x;
    int b = row >> 11;
    int n = row & 2047;
    int yrow = (n & 1) ? (n >> 1) : g_gather[b * NSRC + (n >> 1)];
    const float* src = g_y + ((size_t)b * MM + yrow) * CC;
    float* dst = out + (size_t)row * CC;
    int t = threadIdx.x;                  // 192
    *(float4*)&dst[t * 4] = *(const float4*)&src[t * 4];
}

// ---------------- launcher ----------------
extern "C" void kernel_launch(void* const* d_in, const int* in_sizes, int n_in,
                              void* d_out, int out_size) {
    const float* x    = (const float*)d_in[0];
    const float* Wqkv = (const float*)d_in[1];
    const float* bqkv = (const float*)d_in[2];
    const float* Wo   = (const float*)d_in[3];
    const float* bo   = (const float*)d_in[4];
    float* out = (float*)d_out;

    __half *xm, *qkvb, *attnb, *wq, *wo;
    float* yb;
    cudaGetSymbolAddress((void**)&xm, g_xm);
    cudaGetSymbolAddress((void**)&qkvb, g_qkv);
    cudaGetSymbolAddress((void**)&attnb, g_attn);
    cudaGetSymbolAddress((void**)&yb, g_y);
    cudaGetSymbolAddress((void**)&wq, g_wqkv);
    cudaGetSymbolAddress((void**)&wo, g_wo);

    cudaFuncSetAttribute(match_mma_k, cudaFuncAttributeMaxDynamicSharedMemorySize, 49152);
    cudaFuncSetAttribute(flash_fp16_k, cudaFuncAttributeMaxDynamicSharedMemorySize, FL_SMEM);

    roundcph_k<<<(CC * C3 + 255) / 256, 256>>>(Wqkv, wq, CC * C3);
    roundcph_k<<<(CC * CC + 255) / 256, 256>>>(Wo, wo, CC * CC);
    metric_k<<<BB * NN, 256>>>(x);
    match_mma_k<<<dim3(8, 8, 8), 256, 49152>>>();
    topk_k<<<BB, 1024>>>();
    buildall_k<<<BB * MM, 192>>>(x);
    gemm_fp16_k<<<dim3(C3 / 128, (BB * MM) / 128), 256>>>(xm, wq, bqkv, (void*)qkvb, C3, 1);
    flash_fp16_k<<<dim3(MM / 128, BB * HH), 256, FL_SMEM>>>(qkvb, attnb);
    gemm_fp16_k<<<dim3(CC / 128, (BB * MM) / 128), 256>>>(attnb, wo, bo, (void*)yb, CC, 0);
    unmerge_k<<<BB * NN, 192>>>(out);
}

// round 15
// speedup vs baseline: 1.7545x; 1.0152x over previous
#include <cuda_runtime.h>
#include <cuda_bf16.h>
#include <cuda_fp16.h>
#include <math.h>

#define BB 8
#define NN 2048
#define CC 768
#define HH 12
#define MM 1536
#define RR 512
#define NSRC 1024
#define NDST 1024
#define C3 2304

__device__ __forceinline__ void mma16bf(float c[4], const unsigned a[4], const unsigned b[2]) {
    asm volatile("mma.sync.aligned.m16n8k16.row.col.f32.bf16.bf16.f32 "
        "{%0,%1,%2,%3}, {%4,%5,%6,%7}, {%8,%9}, {%0,%1,%2,%3};"
        : "+f"(c[0]), "+f"(c[1]), "+f"(c[2]), "+f"(c[3])
        : "r"(a[0]), "r"(a[1]), "r"(a[2]), "r"(a[3]), "r"(b[0]), "r"(b[1]));
}
__device__ __forceinline__ void mma16f(float c[4], const unsigned a[4], const unsigned b[2]) {
    asm volatile("mma.sync.aligned.m16n8k16.row.col.f32.f16.f16.f32 "
        "{%0,%1,%2,%3}, {%4,%5,%6,%7}, {%8,%9}, {%0,%1,%2,%3};"
        : "+f"(c[0]), "+f"(c[1]), "+f"(c[2]), "+f"(c[3])
        : "r"(a[0]), "r"(a[1]), "r"(a[2]), "r"(a[3]), "r"(b[0]), "r"(b[1]));
}
__device__ __forceinline__ void ldsm4(unsigned r[4], unsigned addr) {
    asm volatile("ldmatrix.sync.aligned.m8n8.x4.shared.b16 {%0,%1,%2,%3}, [%4];"
        : "=r"(r[0]), "=r"(r[1]), "=r"(r[2]), "=r"(r[3]) : "r"(addr));
}
__device__ __forceinline__ void ldsm4t(unsigned r[4], unsigned addr) {
    asm volatile("ldmatrix.sync.aligned.m8n8.x4.trans.shared.b16 {%0,%1,%2,%3}, [%4];"
        : "=r"(r[0]), "=r"(r[1]), "=r"(r[2]), "=r"(r[3]) : "r"(addr));
}
__device__ __forceinline__ unsigned smem_u32(const void* p) {
    return (unsigned)__cvta_generic_to_shared(p);
}
__device__ __forceinline__ void cp16(unsigned d, const void* s) {
    asm volatile("cp.async.cg.shared.global [%0], [%1], 16;" :: "r"(d), "l"(s));
}
__device__ __forceinline__ void cpcommit() { asm volatile("cp.async.commit_group;"); }
__device__ __forceinline__ void cpwait0()  { asm volatile("cp.async.wait_group 0;"); }
__device__ __forceinline__ unsigned packh2(float lo, float hi) {
    __half2 h = __floats2half2_rn(lo, hi);
    return *reinterpret_cast<unsigned*>(&h);
}

// ---------------- scratch ----------------
__device__ __nv_bfloat16 g_mhib[(size_t)BB * NN * CC];
__device__ __nv_bfloat16 g_mlob[(size_t)BB * NN * CC];
__device__ float g_pmax[BB * 8 * NSRC];
__device__ int   g_pidx[BB * 8 * NSRC];
__device__ int   g_srcidx[BB * RR];
__device__ int   g_unmidx[BB * RR];
__device__ int   g_gather[BB * NSRC];
__device__ int   g_lhead[BB * NSRC];
__device__ int   g_lnext[BB * RR];
__device__ __half g_xm[(size_t)BB * MM * CC];
__device__ __half g_qkv[(size_t)BB * MM * C3];
__device__ __half g_attn[(size_t)BB * MM * CC];
__device__ __half g_wqkv[CC * C3];
__device__ __half g_wo[CC * CC];

// ---------------- 0. pre-round both weights to fp16 (one launch) ----------------
__global__ void roundboth_k(const float* __restrict__ w1, __half* __restrict__ d1, int n1,
                            const float* __restrict__ w2, __half* __restrict__ d2, int n2) {
    int i = blockIdx.x * 256 + threadIdx.x;
    if (i < n1) d1[i] = __float2half_rn(w1[i]);
    else if (i < n1 + n2) d2[i - n1] = __float2half_rn(w2[i - n1]);
}

// ---------------- 1. normalized metric -> bf16 hi/lo (verified R11) ----------------
__global__ void metric_k(const float* __restrict__ x) {
    int row = blockIdx.x;
    int tid = threadIdx.x;                 // 256
    const float* p = x + (size_t)row * CC;
    float v0 = p[tid], v1 = p[tid + 256], v2 = p[tid + 512];
    float s = v0 * v0 + v1 * v1 + v2 * v2;
    __shared__ float red[256];
    red[tid] = s; __syncthreads();
    for (int o = 128; o > 0; o >>= 1) {
        if (tid < o) red[tid] += red[tid + o];
        __syncthreads();
    }
    float nrm = sqrtf(red[0]);
    size_t off = (size_t)row * CC;
#pragma unroll
    for (int q = 0; q < 3; q++) {
        float m = (q == 0 ? v0 : q == 1 ? v1 : v2) / nrm;
        __nv_bfloat16 h = __float2bfloat16_rn(m);
        __nv_bfloat16 lo = __float2bfloat16_rn(m - __bfloat162float(h));
        g_mhib[off + tid + q * 256] = h;
        g_mlob[off + tid + q * 256] = lo;
    }
}

// ---------------- 2. matching via 3xBF16 k16 MMA (R11/R14-verified, verbatim) ----------------
#define MT_TILE 6144
__global__ __launch_bounds__(256, 2) void match_mma_k() {
    extern __shared__ float dsm[];
    char* smb = (char*)dsm;
    unsigned sAH = smem_u32(smb);
    unsigned sAL = sAH + 2 * MT_TILE;
    unsigned sBH = sAH + 4 * MT_TILE;
    unsigned sBL = sAH + 6 * MT_TILE;

    int dt = blockIdx.x, st = blockIdx.y, b = blockIdx.z;
    int tid = threadIdx.x;
    int w = tid >> 5, l = tid & 31;
    int wm = w & 3, wn = w >> 2;
    int lr = l >> 2, lc = l & 3;

    size_t bbase = (size_t)b * NN * CC;
    int r = tid >> 1, half = tid & 1;
    size_t aoff = bbase + (size_t)(2 * (st * 128 + r)) * CC + half * 8;
    size_t boff = bbase + (size_t)(2 * (dt * 128 + r) + 1) * CC + half * 8;
    const __nv_bfloat16* aH = g_mhib + aoff;
    const __nv_bfloat16* aL = g_mlob + aoff;
    const __nv_bfloat16* bH = g_mhib + boff;
    const __nv_bfloat16* bL = g_mlob + boff;
    unsigned dstoff = (unsigned)(r * 48 + half * 16);

    unsigned aAdr = (unsigned)((wm * 32 + (l & 15)) * 48 + ((l >> 4) & 1) * 16);
    unsigned bAdr = (unsigned)((wn * 64 + (l & 7) + ((l >> 4) & 1) * 8) * 48 + ((l >> 3) & 1) * 16);

    float acc[2][8][4] = {};

    auto issue = [&](int c, int buf) {
        unsigned d = dstoff + (unsigned)buf * MT_TILE;
        cp16(sAH + d, aH + c * 16);
        cp16(sAL + d, aL + c * 16);
        cp16(sBH + d, bH + c * 16);
        cp16(sBL + d, bL + c * 16);
    };

    issue(0, 0); cpcommit();
    int buf = 0;
    for (int c = 0; c < 48; c++) {
        cpwait0();
        __syncthreads();
        if (c + 1 < 48) { issue(c + 1, buf ^ 1); cpcommit(); }
        unsigned bo = (unsigned)buf * MT_TILE;
        unsigned ah[2][4], al[2][4];
        ldsm4(ah[0], sAH + bo + aAdr);
        ldsm4(ah[1], sAH + bo + aAdr + 16 * 48);
        ldsm4(al[0], sAL + bo + aAdr);
        ldsm4(al[1], sAL + bo + aAdr + 16 * 48);
        unsigned bh4[4][4];
#pragma unroll
        for (int ntp = 0; ntp < 4; ntp++) ldsm4(bh4[ntp], sBH + bo + bAdr + ntp * 16 * 48);
#pragma unroll
        for (int ntp = 0; ntp < 4; ntp++) {      // hi*hi
            mma16bf(acc[0][2 * ntp],     ah[0], bh4[ntp]);
            mma16bf(acc[1][2 * ntp],     ah[1], bh4[ntp]);
            mma16bf(acc[0][2 * ntp + 1], ah[0], bh4[ntp] + 2);
            mma16bf(acc[1][2 * ntp + 1], ah[1], bh4[ntp] + 2);
        }
#pragma unroll
        for (int ntp = 0; ntp < 4; ntp++) {      // lo*hi
            mma16bf(acc[0][2 * ntp],     al[0], bh4[ntp]);
            mma16bf(acc[1][2 * ntp],     al[1], bh4[ntp]);
            mma16bf(acc[0][2 * ntp + 1], al[0], bh4[ntp] + 2);
            mma16bf(acc[1][2 * ntp + 1], al[1], bh4[ntp] + 2);
        }
#pragma unroll
        for (int ntp = 0; ntp < 4; ntp++) {      // hi*lo
            unsigned bl4[4];
            ldsm4(bl4, sBL + bo + bAdr + ntp * 16 * 48);
            mma16bf(acc[0][2 * ntp],     ah[0], bl4);
            mma16bf(acc[1][2 * ntp],     ah[1], bl4);
            mma16bf(acc[0][2 * ntp + 1], ah[0], bl4 + 2);
            mma16bf(acc[1][2 * ntp + 1], ah[1], bl4 + 2);
        }
        buf ^= 1;
    }
    float* spm = dsm;
    int*   spi = (int*)(dsm + 256);
    __syncthreads();
#pragma unroll
    for (int mt = 0; mt < 2; mt++) {
        float bv0 = -INFINITY, bv1 = -INFINITY;
        int bi0 = 0, bi1 = 0;
#pragma unroll
        for (int nt = 0; nt < 8; nt++) {
            int cb = dt * 128 + wn * 64 + nt * 8 + 2 * lc;
            if (acc[mt][nt][0] > bv0) { bv0 = acc[mt][nt][0]; bi0 = cb; }
            if (acc[mt][nt][1] > bv0) { bv0 = acc[mt][nt][1]; bi0 = cb + 1; }
            if (acc[mt][nt][2] > bv1) { bv1 = acc[mt][nt][2]; bi1 = cb; }
            if (acc[mt][nt][3] > bv1) { bv1 = acc[mt][nt][3]; bi1 = cb + 1; }
        }
#pragma unroll
        for (int off = 1; off <= 2; off <<= 1) {
            float ov = __shfl_xor_sync(0xffffffffu, bv0, off);
            int   oi = __shfl_xor_sync(0xffffffffu, bi0, off);
            if (ov > bv0 || (ov == bv0 && oi < bi0)) { bv0 = ov; bi0 = oi; }
            ov = __shfl_xor_sync(0xffffffffu, bv1, off);
            oi = __shfl_xor_sync(0xffffffffu, bi1, off);
            if (ov > bv1 || (ov == bv1 && oi < bi1)) { bv1 = ov; bi1 = oi; }
        }
        if (lc == 0) {
            int r0 = wm * 32 + mt * 16 + lr;
            spm[wn * 128 + r0] = bv0;  spi[wn * 128 + r0] = bi0;
            spm[wn * 128 + r0 + 8] = bv1; spi[wn * 128 + r0 + 8] = bi1;
        }
    }
    __syncthreads();
    if (tid < 128) {
        float v0 = spm[tid], v1 = spm[128 + tid];
        int   i0 = spi[tid], i1 = spi[128 + tid];
        if (v1 > v0) { v0 = v1; i0 = i1; }
        g_pmax[(b * 8 + dt) * NSRC + st * 128 + tid] = v0;
        g_pidx[(b * 8 + dt) * NSRC + st * 128 + tid] = i0;
    }
}

// ---------------- 3. top-k (verified) ----------------
__global__ void topk_k() {
    __shared__ unsigned long long key[1024];
    __shared__ int nidx[1024];
    __shared__ int mrg[1024];
    __shared__ int scn[1024];
    int b = blockIdx.x, tid = threadIdx.x;   // 1024

    float bv = g_pmax[(b * 8) * NSRC + tid];
    int   bi = g_pidx[(b * 8) * NSRC + tid];
#pragma unroll
    for (int dt = 1; dt < 8; dt++) {
        float v = g_pmax[(b * 8 + dt) * NSRC + tid];
        if (v > bv) { bv = v; bi = g_pidx[(b * 8 + dt) * NSRC + tid]; }
    }
    nidx[tid] = bi;
    {
        unsigned u = __float_as_uint(bv);
        u = (u & 0x80000000u) ? ~u : (u | 0x80000000u);
        key[tid] = ((unsigned long long)(~u) << 32) | (unsigned)tid;
    }
    mrg[tid] = 0;
    g_lhead[b * NSRC + tid] = -1;
    __syncthreads();
    for (int k = 2; k <= 1024; k <<= 1)
        for (int j = k >> 1; j > 0; j >>= 1) {
            int p = tid ^ j;
            if (p > tid) {
                bool up = ((tid & k) == 0);
                unsigned long long a = key[tid], c2 = key[p];
                if ((a > c2) == up) { key[tid] = c2; key[p] = a; }
            }
            __syncthreads();
        }
    if (tid < 512) {
        int s = (int)(key[tid] & 0xffffffffu);
        g_srcidx[b * RR + tid] = s;
        mrg[s] = 1;
        int d = nidx[s];
        g_lnext[b * RR + tid] = atomicExch(&g_lhead[b * NSRC + d], tid);
    }
    __syncthreads();
    int um = mrg[tid] ? 0 : 1;
    scn[tid] = um; __syncthreads();
    for (int off = 1; off < 1024; off <<= 1) {
        int v = scn[tid];
        int v2 = (tid >= off) ? scn[tid - off] : 0;
        __syncthreads();
        scn[tid] = v + v2; __syncthreads();
    }
    int rnk = scn[tid] - um;
    if (um) { g_unmidx[b * RR + rnk] = tid; g_gather[b * NSRC + tid] = NDST + rnk; }
    else    { g_gather[b * NSRC + tid] = nidx[tid]; }
}

// ---------------- 4. fused merge build (emits fp16 xm) ----------------
__global__ void buildall_k(const float* __restrict__ x) {
    int row = blockIdx.x;
    int b = row / MM, j = row - b * MM;
    int t = threadIdx.x;                    // 192
    __half* dst = g_xm + (size_t)row * CC;
    if (j >= NDST) {
        int s = g_unmidx[b * RR + (j - NDST)];
        const float* src = x + ((size_t)b * NN + 2 * s) * CC;
        float4 v = *(const float4*)&src[t * 4];
        uint2 o = { packh2(v.x, v.y), packh2(v.z, v.w) };
        *(uint2*)&dst[t * 4] = o;
        return;
    }
    const float* dsrc = x + ((size_t)b * NN + 2 * j + 1) * CC;
    float4 v = *(const float4*)&dsrc[t * 4];
    float cntf = 1.f;
    int it = g_lhead[b * NSRC + j];
    while (it >= 0) {
        int s = g_srcidx[b * RR + it];
        float4 sv = *(const float4*)&x[((size_t)b * NN + 2 * s) * CC + t * 4];
        v.x += sv.x; v.y += sv.y; v.z += sv.z; v.w += sv.w;
        cntf += 1.f;
        it = g_lnext[b * RR + it];
    }
    float inv = 1.f / cntf;
    uint2 o = { packh2(v.x * inv, v.y * inv), packh2(v.z * inv, v.w * inv) };
    *(uint2*)&dst[t * 4] = o;
}

// ---------------- 5. fp16 GEMM k16 (R14-verified mainloop) ----------------
// mode 1: fp16 output to Cv. mode 2: fused-unmerge fp32 scatter to out (Cv).
__global__ __launch_bounds__(256, 2) void gemm_fp16_k(
        const __half* __restrict__ A, const __half* __restrict__ Bm,
        const float* __restrict__ bias, void* Cv, int Nd, int mode) {
    __shared__ __align__(16) char gsm[2 * 10240 + 2 * 8704];
    unsigned sA = smem_u32(gsm);
    unsigned sB = sA + 20480;
    int tid = threadIdx.x;
    int w = tid >> 5, l = tid & 31;
    int wm = w & 3, wn = w >> 2;
    int lr = l >> 2, lc = l & 3;
    int bm = blockIdx.y * 128, bn = blockIdx.x * 128;
    float acc[2][8][4] = {};

    int ar = tid >> 1, ah = tid & 1;
    const __half* Ap = A + (size_t)(bm + ar) * CC + ah * 16;
    unsigned adst = sA + (unsigned)(ar * 80 + ah * 32);
    int br = tid >> 3, bc = tid & 7;
    const __half* Bp = Bm + bn + bc * 16;
    unsigned bdst = sB + (unsigned)(br * 272 + bc * 32);

    unsigned aAdr = sA + (unsigned)((wm * 32 + (l & 15)) * 80 + ((l >> 4) & 1) * 16);
    unsigned bAdr = sB + (unsigned)(((l & 7) + ((l >> 3) & 1) * 8) * 272
                         + (wn * 64 + ((l >> 4) & 1) * 8) * 2);

    auto issue = [&](int c, int buf) {
        const __half* a = Ap + c * 32;
        cp16(adst + buf * 10240u, a);
        cp16(adst + buf * 10240u + 16, a + 8);
        const __half* bsrc = Bp + (size_t)(c * 32 + br) * Nd;
        cp16(bdst + buf * 8704u, bsrc);
        cp16(bdst + buf * 8704u + 16, bsrc + 8);
    };

    issue(0, 0); cpcommit();
    int buf = 0;
    for (int c = 0; c < 24; c++) {
        cpwait0();
        __syncthreads();
        if (c + 1 < 24) { issue(c + 1, buf ^ 1); cpcommit(); }
        unsigned ao = buf * 10240u, bo = buf * 8704u;
#pragma unroll
        for (int ks = 0; ks < 2; ks++) {
            unsigned a0[4], a1[4];
            ldsm4(a0, aAdr + ao + ks * 32);
            ldsm4(a1, aAdr + ao + 16 * 80 + ks * 32);
#pragma unroll
            for (int ntp = 0; ntp < 4; ntp++) {
                unsigned bq[4];
                ldsm4t(bq, bAdr + bo + ks * 16 * 272 + ntp * 32);
                mma16f(acc[0][2 * ntp],     a0, bq);
                mma16f(acc[1][2 * ntp],     a1, bq);
                mma16f(acc[0][2 * ntp + 1], a0, bq + 2);
                mma16f(acc[1][2 * ntp + 1], a1, bq + 2);
            }
        }
        buf ^= 1;
    }
    if (mode == 1) {
        __half* C = (__half*)Cv;
#pragma unroll
        for (int mt = 0; mt < 2; mt++) {
            int r0 = bm + wm * 32 + mt * 16 + lr;
#pragma unroll
            for (int nt = 0; nt < 8; nt++) {
                int c = bn + wn * 64 + nt * 8 + 2 * lc;
                float b0 = bias[c], b1 = bias[c + 1];
                *(unsigned*)&C[(size_t)r0 * Nd + c] =
                    packh2(acc[mt][nt][0] + b0, acc[mt][nt][1] + b1);
                *(unsigned*)&C[(size_t)(r0 + 8) * Nd + c] =
                    packh2(acc[mt][nt][2] + b0, acc[mt][nt][3] + b1);
            }
        }
    } else {
        // fused unmerge: scatter fp32 rows directly into out
        float* outp = (float*)Cv;
        int b2 = bm / MM;
        float bx[8][2];
#pragma unroll
        for (int nt = 0; nt < 8; nt++) {
            int c = bn + wn * 64 + nt * 8 + 2 * lc;
            bx[nt][0] = bias[c]; bx[nt][1] = bias[c + 1];
        }
#pragma unroll
        for (int mt = 0; mt < 2; mt++) {
#pragma unroll
            for (int hf = 0; hf < 2; hf++) {
                int rrow = bm + wm * 32 + mt * 16 + lr + hf * 8;
                int j = rrow - b2 * MM;
                float v[8][2];
#pragma unroll
                for (int nt = 0; nt < 8; nt++) {
                    v[nt][0] = acc[mt][nt][2 * hf]     + bx[nt][0];
                    v[nt][1] = acc[mt][nt][2 * hf + 1] + bx[nt][1];
                }
                int n0 = (j < NDST) ? (2 * j + 1)
                                    : 2 * g_unmidx[b2 * RR + (j - NDST)];
                float* dp = outp + ((size_t)b2 * NN + n0) * CC + bn + wn * 64 + 2 * lc;
#pragma unroll
                for (int nt = 0; nt < 8; nt++)
                    *(float2*)&dp[nt * 8] = make_float2(v[nt][0], v[nt][1]);
                if (j < NDST) {
                    for (int it = g_lhead[b2 * NSRC + j]; it >= 0; it = g_lnext[b2 * RR + it]) {
                        int s = g_srcidx[b2 * RR + it];
                        float* dp2 = outp + ((size_t)b2 * NN + 2 * s) * CC + bn + wn * 64 + 2 * lc;
#pragma unroll
                        for (int nt = 0; nt < 8; nt++)
                            *(float2*)&dp2[nt * 8] = make_float2(v[nt][0], v[nt][1]);
                    }
                }
            }
        }
    }
}

// ---------------- 6. flash attention fp16 k16 (R14-verified, verbatim) ----------------
#define FL_SMEM (18432 + 2 * 9216 + 2 * 9216)
__global__ __launch_bounds__(256, 2) void flash_fp16_k(
        const __half* __restrict__ qkv, __half* __restrict__ o) {
    extern __shared__ char fsm[];
    unsigned sQ = smem_u32(fsm);
    unsigned sK = sQ + 18432;
    unsigned sV = sK + 2 * 9216;

    int qt = blockIdx.x, bh = blockIdx.y;
    int b = bh / HH, h = bh % HH;
    const __half* base = qkv + (size_t)b * MM * C3 + h * 64;
    int tid = threadIdx.x;
    int w = tid >> 5, l = tid & 31;
    int lr = l >> 2, lc = l & 3;
    int mr0 = w * 16 + lr;

    unsigned qAdr = sQ + (unsigned)((w * 16 + (l & 15)) * 144 + ((l >> 4) & 1) * 16);
    unsigned kAdr = sK + (unsigned)(((l & 7) + ((l >> 4) & 1) * 8) * 144 + ((l >> 3) & 1) * 16);
    unsigned vAdr = sV + (unsigned)(((l & 7) + ((l >> 3) & 1) * 8) * 144 + ((l >> 4) & 1) * 16);

    {   // Q fill with exact *0.125 scale
        int r = tid >> 1, hf = (tid & 1) * 32;
        const __half2* qp = (const __half2*)(base + (size_t)(qt * 128 + r) * C3 + hf);
        __half2* dq = (__half2*)(fsm + r * 144 + hf * 2);
        __half2 sc = __floats2half2_rn(0.125f, 0.125f);
#pragma unroll
        for (int i = 0; i < 16; i++) dq[i] = __hmul2(qp[i], sc);
    }
    int kr = tid >> 2, kq = (tid & 3) * 16;
    unsigned kdst = sK + (unsigned)(kr * 144 + (tid & 3) * 32);
    unsigned vdst = sV + (unsigned)(kr * 144 + (tid & 3) * 32);
    const __half* kgp = base + CC + (size_t)kr * C3 + kq;
    const __half* vgp = base + 2 * CC + (size_t)kr * C3 + kq;

    auto issue = [&](int kt, int buf) {
        const __half* ks = kgp + (size_t)kt * 64 * C3;
        const __half* vs = vgp + (size_t)kt * 64 * C3;
        cp16(kdst + buf * 9216u, ks);  cp16(kdst + buf * 9216u + 16, ks + 8);
        cp16(vdst + buf * 9216u, vs);  cp16(vdst + buf * 9216u + 16, vs + 8);
        cpcommit();
    };
    issue(0, 0);

    float om[8][4] = {};
    float m0 = -INFINITY, m1 = -INFINITY, l0 = 0.f, l1 = 0.f;

    for (int kt = 0; kt < 24; kt++) {
        int buf = kt & 1;
        cpwait0();
        __syncthreads();
        if (kt + 1 < 24) issue(kt + 1, buf ^ 1);
        float s[8][4] = {};
#pragma unroll
        for (int ks = 0; ks < 4; ks++) {
            unsigned af[4];
            ldsm4(af, qAdr + ks * 32);
#pragma unroll
            for (int ntp = 0; ntp < 4; ntp++) {
                unsigned bq[4];
                ldsm4(bq, kAdr + buf * 9216u + ntp * 2304 + ks * 32);
                mma16f(s[2 * ntp],     af, bq);
                mma16f(s[2 * ntp + 1], af, bq + 2);
            }
        }
        float mx0 = -INFINITY, mx1 = -INFINITY;
#pragma unroll
        for (int nt = 0; nt < 8; nt++) {
            mx0 = fmaxf(mx0, fmaxf(s[nt][0], s[nt][1]));
            mx1 = fmaxf(mx1, fmaxf(s[nt][2], s[nt][3]));
        }
        mx0 = fmaxf(mx0, __shfl_xor_sync(0xffffffffu, mx0, 1));
        mx0 = fmaxf(mx0, __shfl_xor_sync(0xffffffffu, mx0, 2));
        mx1 = fmaxf(mx1, __shfl_xor_sync(0xffffffffu, mx1, 1));
        mx1 = fmaxf(mx1, __shfl_xor_sync(0xffffffffu, mx1, 2));
        float mn0 = fmaxf(m0, mx0), mn1 = fmaxf(m1, mx1);
        float al0 = __expf(m0 - mn0), al1 = __expf(m1 - mn1);
        m0 = mn0; m1 = mn1;
        float rs0 = 0.f, rs1 = 0.f;
#pragma unroll
        for (int nt = 0; nt < 8; nt++) {
            s[nt][0] = __expf(s[nt][0] - mn0); rs0 += s[nt][0];
            s[nt][1] = __expf(s[nt][1] - mn0); rs0 += s[nt][1];
            s[nt][2] = __expf(s[nt][2] - mn1); rs1 += s[nt][2];
            s[nt][3] = __expf(s[nt][3] - mn1); rs1 += s[nt][3];
        }
        rs0 += __shfl_xor_sync(0xffffffffu, rs0, 1);
        rs0 += __shfl_xor_sync(0xffffffffu, rs0, 2);
        rs1 += __shfl_xor_sync(0xffffffffu, rs1, 1);
        rs1 += __shfl_xor_sync(0xffffffffu, rs1, 2);
        l0 = l0 * al0 + rs0; l1 = l1 * al1 + rs1;
#pragma unroll
        for (int nt = 0; nt < 8; nt++) {
            om[nt][0] *= al0; om[nt][1] *= al0;
            om[nt][2] *= al1; om[nt][3] *= al1;
        }
#pragma unroll
        for (int ks = 0; ks < 4; ks++) {
            unsigned af[4] = {
                packh2(s[2 * ks][0],     s[2 * ks][1]),
                packh2(s[2 * ks][2],     s[2 * ks][3]),
                packh2(s[2 * ks + 1][0], s[2 * ks + 1][1]),
                packh2(s[2 * ks + 1][2], s[2 * ks + 1][3])
            };
#pragma unroll
            for (int ntp = 0; ntp < 4; ntp++) {
                unsigned bq[4];
                ldsm4t(bq, vAdr + buf * 9216u + ks * 2304 + ntp * 32);
                mma16f(om[2 * ntp],     af, bq);
                mma16f(om[2 * ntp + 1], af, bq + 2);
            }
        }
    }
    float i0 = 1.f / l0, i1 = 1.f / l1;
    size_t row0 = (size_t)b * MM + qt * 128 + mr0;
#pragma unroll
    for (int nt = 0; nt < 8; nt++) {
        int c = h * 64 + nt * 8 + 2 * lc;
        *(unsigned*)&o[row0 * CC + c] = packh2(om[nt][0] * i0, om[nt][1] * i0);
        *(unsigned*)&o[(row0 + 8) * CC + c] = packh2(om[nt][2] * i1, om[nt][3] * i1);
    }
}

// ---------------- launcher ----------------
extern "C" void kernel_launch(void* const* d_in, const int* in_sizes, int n_in,
                              void* d_out, int out_size) {
    const float* x    = (const float*)d_in[0];
    const float* Wqkv = (const float*)d_in[1];
    const float* bqkv = (const float*)d_in[2];
    const float* Wo   = (const float*)d_in[3];
    const float* bo   = (const float*)d_in[4];
    float* out = (float*)d_out;

    __half *xm, *qkvb, *attnb, *wq, *wo;
    cudaGetSymbolAddress((void**)&xm, g_xm);
    cudaGetSymbolAddress((void**)&qkvb, g_qkv);
    cudaGetSymbolAddress((void**)&attnb, g_attn);
    cudaGetSymbolAddress((void**)&wq, g_wqkv);
    cudaGetSymbolAddress((void**)&wo, g_wo);

    cudaFuncSetAttribute(match_mma_k, cudaFuncAttributeMaxDynamicSharedMemorySize, 49152);
    cudaFuncSetAttribute(flash_fp16_k, cudaFuncAttributeMaxDynamicSharedMemorySize, FL_SMEM);

    int nw = CC * C3 + CC * CC;
    roundboth_k<<<(nw + 255) / 256, 256>>>(Wqkv, wq, CC * C3, Wo, wo, CC * CC);
    metric_k<<<BB * NN, 256>>>(x);
    match_mma_k<<<dim3(8, 8, 8), 256, 49152>>>();
    topk_k<<<BB, 1024>>>();
    buildall_k<<<BB * MM, 192>>>(x);
    gemm_fp16_k<<<dim3(C3 / 128, (BB * MM) / 128), 256>>>(xm, wq, bqkv, (void*)qkvb, C3, 1);
    flash_fp16_k<<<dim3(MM / 128, BB * HH), 256, FL_SMEM>>>(qkvb, attnb);
    gemm_fp16_k<<<dim3(CC / 128, (BB * MM) / 128), 256>>>(attnb, wo, bo, (void*)out, CC, 2);
}

// round 17
// speedup vs baseline: 1.7891x; 1.0197x over previous
#include <cuda_runtime.h>
#include <cuda_bf16.h>
#include <cuda_fp16.h>
#include <math.h>

#define BB 8
#define NN 2048
#define CC 768
#define HH 12
#define MM 1536
#define RR 512
#define NSRC 1024
#define NDST 1024
#define C3 2304

__device__ __forceinline__ void mma16bf(float c[4], const unsigned a[4], const unsigned b[2]) {
    asm volatile("mma.sync.aligned.m16n8k16.row.col.f32.bf16.bf16.f32 "
        "{%0,%1,%2,%3}, {%4,%5,%6,%7}, {%8,%9}, {%0,%1,%2,%3};"
        : "+f"(c[0]), "+f"(c[1]), "+f"(c[2]), "+f"(c[3])
        : "r"(a[0]), "r"(a[1]), "r"(a[2]), "r"(a[3]), "r"(b[0]), "r"(b[1]));
}
__device__ __forceinline__ void mma16f(float c[4], const unsigned a[4], const unsigned b[2]) {
    asm volatile("mma.sync.aligned.m16n8k16.row.col.f32.f16.f16.f32 "
        "{%0,%1,%2,%3}, {%4,%5,%6,%7}, {%8,%9}, {%0,%1,%2,%3};"
        : "+f"(c[0]), "+f"(c[1]), "+f"(c[2]), "+f"(c[3])
        : "r"(a[0]), "r"(a[1]), "r"(a[2]), "r"(a[3]), "r"(b[0]), "r"(b[1]));
}
__device__ __forceinline__ void ldsm4(unsigned r[4], unsigned addr) {
    asm volatile("ldmatrix.sync.aligned.m8n8.x4.shared.b16 {%0,%1,%2,%3}, [%4];"
        : "=r"(r[0]), "=r"(r[1]), "=r"(r[2]), "=r"(r[3]) : "r"(addr));
}
__device__ __forceinline__ void ldsm4t(unsigned r[4], unsigned addr) {
    asm volatile("ldmatrix.sync.aligned.m8n8.x4.trans.shared.b16 {%0,%1,%2,%3}, [%4];"
        : "=r"(r[0]), "=r"(r[1]), "=r"(r[2]), "=r"(r[3]) : "r"(addr));
}
__device__ __forceinline__ unsigned smem_u32(const void* p) {
    return (unsigned)__cvta_generic_to_shared(p);
}
__device__ __forceinline__ void cp16(unsigned d, const void* s) {
    asm volatile("cp.async.cg.shared.global [%0], [%1], 16;" :: "r"(d), "l"(s));
}
__device__ __forceinline__ void cpcommit() { asm volatile("cp.async.commit_group;"); }
__device__ __forceinline__ void cpwait0()  { asm volatile("cp.async.wait_group 0;"); }
__device__ __forceinline__ unsigned packh2(float lo, float hi) {
    __half2 h = __floats2half2_rn(lo, hi);
    return *reinterpret_cast<unsigned*>(&h);
}

// ---------------- scratch ----------------
__device__ __nv_bfloat16 g_mhib[(size_t)BB * NN * CC];
__device__ __nv_bfloat16 g_mlob[(size_t)BB * NN * CC];
__device__ float g_pmax[BB * 8 * NSRC];
__device__ int   g_pidx[BB * 8 * NSRC];
__device__ int   g_srcidx[BB * RR];
__device__ int   g_unmidx[BB * RR];
__device__ int   g_lhead[BB * NSRC];
__device__ int   g_lnext[BB * RR];
__device__ __half g_xm[(size_t)BB * MM * CC];
__device__ __half g_qkv[(size_t)BB * MM * C3];
__device__ __half g_attn[(size_t)BB * MM * CC];
__device__ __half g_wqkv[CC * C3];
__device__ __half g_wo[CC * CC];

// ---------------- 0. pre-round both weights to fp16 (one launch) ----------------
__global__ void roundboth_k(const float* __restrict__ w1, __half* __restrict__ d1, int n1,
                            const float* __restrict__ w2, __half* __restrict__ d2, int n2) {
    int i = blockIdx.x * 256 + threadIdx.x;
    if (i < n1) d1[i] = __float2half_rn(w1[i]);
    else if (i < n1 + n2) d2[i - n1] = __float2half_rn(w2[i - n1]);
}

// ---------------- 1. normalized metric -> bf16 hi/lo, warp-per-row ----------------
__global__ void metric_k(const float* __restrict__ x) {
    int row = blockIdx.x * 8 + (threadIdx.x >> 5);   // grid 2048, 8 warps/block
    int l = threadIdx.x & 31;
    const float4* p = (const float4*)(x + (size_t)row * CC);
    float4 v[6];
    float s = 0.f;
#pragma unroll
    for (int i = 0; i < 6; i++) {
        v[i] = p[i * 32 + l];
        s += v[i].x * v[i].x + v[i].y * v[i].y + v[i].z * v[i].z + v[i].w * v[i].w;
    }
#pragma unroll
    for (int off = 16; off; off >>= 1)
        s += __shfl_xor_sync(0xffffffffu, s, off);
    float nrm = sqrtf(s);
    size_t base = (size_t)row * CC;
#pragma unroll
    for (int i = 0; i < 6; i++) {
        float m[4] = { v[i].x / nrm, v[i].y / nrm, v[i].z / nrm, v[i].w / nrm };
        __nv_bfloat16 h[4], lo[4];
#pragma unroll
        for (int q = 0; q < 4; q++) {
            h[q]  = __float2bfloat16_rn(m[q]);
            lo[q] = __float2bfloat16_rn(m[q] - __bfloat162float(h[q]));
        }
        *(uint2*)&g_mhib[base + (i * 32 + l) * 4] =
            make_uint2(((unsigned)*(unsigned short*)&h[1] << 16) | *(unsigned short*)&h[0],
                       ((unsigned)*(unsigned short*)&h[3] << 16) | *(unsigned short*)&h[2]);
        *(uint2*)&g_mlob[base + (i * 32 + l) * 4] =
            make_uint2(((unsigned)*(unsigned short*)&lo[1] << 16) | *(unsigned short*)&lo[0],
                       ((unsigned)*(unsigned short*)&lo[3] << 16) | *(unsigned short*)&lo[2]);
    }
}

// ---------------- 2. matching via 3xBF16 k16 MMA (R11/R14-verified, verbatim) ----------------
#define MT_TILE 6144
__global__ __launch_bounds__(256, 2) void match_mma_k() {
    extern __shared__ float dsm[];
    char* smb = (char*)dsm;
    unsigned sAH = smem_u32(smb);
    unsigned sAL = sAH + 2 * MT_TILE;
    unsigned sBH = sAH + 4 * MT_TILE;
    unsigned sBL = sAH + 6 * MT_TILE;

    int dt = blockIdx.x, st = blockIdx.y, b = blockIdx.z;
    int tid = threadIdx.x;
    int w = tid >> 5, l = tid & 31;
    int wm = w & 3, wn = w >> 2;
    int lr = l >> 2, lc = l & 3;

    size_t bbase = (size_t)b * NN * CC;
    int r = tid >> 1, half = tid & 1;
    size_t aoff = bbase + (size_t)(2 * (st * 128 + r)) * CC + half * 8;
    size_t boff = bbase + (size_t)(2 * (dt * 128 + r) + 1) * CC + half * 8;
    const __nv_bfloat16* aH = g_mhib + aoff;
    const __nv_bfloat16* aL = g_mlob + aoff;
    const __nv_bfloat16* bH = g_mhib + boff;
    const __nv_bfloat16* bL = g_mlob + boff;
    unsigned dstoff = (unsigned)(r * 48 + half * 16);

    unsigned aAdr = (unsigned)((wm * 32 + (l & 15)) * 48 + ((l >> 4) & 1) * 16);
    unsigned bAdr = (unsigned)((wn * 64 + (l & 7) + ((l >> 4) & 1) * 8) * 48 + ((l >> 3) & 1) * 16);

    float acc[2][8][4] = {};

    auto issue = [&](int c, int buf) {
        unsigned d = dstoff + (unsigned)buf * MT_TILE;
        cp16(sAH + d, aH + c * 16);
        cp16(sAL + d, aL + c * 16);
        cp16(sBH + d, bH + c * 16);
        cp16(sBL + d, bL + c * 16);
    };

    issue(0, 0); cpcommit();
    int buf = 0;
    for (int c = 0; c < 48; c++) {
        cpwait0();
        __syncthreads();
        if (c + 1 < 48) { issue(c + 1, buf ^ 1); cpcommit(); }
        unsigned bo = (unsigned)buf * MT_TILE;
        unsigned ah[2][4], al[2][4];
        ldsm4(ah[0], sAH + bo + aAdr);
        ldsm4(ah[1], sAH + bo + aAdr + 16 * 48);
        ldsm4(al[0], sAL + bo + aAdr);
        ldsm4(al[1], sAL + bo + aAdr + 16 * 48);
        unsigned bh4[4][4];
#pragma unroll
        for (int ntp = 0; ntp < 4; ntp++) ldsm4(bh4[ntp], sBH + bo + bAdr + ntp * 16 * 48);
#pragma unroll
        for (int ntp = 0; ntp < 4; ntp++) {      // hi*hi
            mma16bf(acc[0][2 * ntp],     ah[0], bh4[ntp]);
            mma16bf(acc[1][2 * ntp],     ah[1], bh4[ntp]);
            mma16bf(acc[0][2 * ntp + 1], ah[0], bh4[ntp] + 2);
            mma16bf(acc[1][2 * ntp + 1], ah[1], bh4[ntp] + 2);
        }
#pragma unroll
        for (int ntp = 0; ntp < 4; ntp++) {      // lo*hi
            mma16bf(acc[0][2 * ntp],     al[0], bh4[ntp]);
            mma16bf(acc[1][2 * ntp],     al[1], bh4[ntp]);
            mma16bf(acc[0][2 * ntp + 1], al[0], bh4[ntp] + 2);
            mma16bf(acc[1][2 * ntp + 1], al[1], bh4[ntp] + 2);
        }
#pragma unroll
        for (int ntp = 0; ntp < 4; ntp++) {      // hi*lo
            unsigned bl4[4];
            ldsm4(bl4, sBL + bo + bAdr + ntp * 16 * 48);
            mma16bf(acc[0][2 * ntp],     ah[0], bl4);
            mma16bf(acc[1][2 * ntp],     ah[1], bl4);
            mma16bf(acc[0][2 * ntp + 1], ah[0], bl4 + 2);
            mma16bf(acc[1][2 * ntp + 1], ah[1], bl4 + 2);
        }
        buf ^= 1;
    }
    float* spm = dsm;
    int*   spi = (int*)(dsm + 256);
    __syncthreads();
#pragma unroll
    for (int mt = 0; mt < 2; mt++) {
        float bv0 = -INFINITY, bv1 = -INFINITY;
        int bi0 = 0, bi1 = 0;
#pragma unroll
        for (int nt = 0; nt < 8; nt++) {
            int cb = dt * 128 + wn * 64 + nt * 8 + 2 * lc;
            if (acc[mt][nt][0] > bv0) { bv0 = acc[mt][nt][0]; bi0 = cb; }
            if (acc[mt][nt][1] > bv0) { bv0 = acc[mt][nt][1]; bi0 = cb + 1; }
            if (acc[mt][nt][2] > bv1) { bv1 = acc[mt][nt][2]; bi1 = cb; }
            if (acc[mt][nt][3] > bv1) { bv1 = acc[mt][nt][3]; bi1 = cb + 1; }
        }
#pragma unroll
        for (int off = 1; off <= 2; off <<= 1) {
            float ov = __shfl_xor_sync(0xffffffffu, bv0, off);
            int   oi = __shfl_xor_sync(0xffffffffu, bi0, off);
            if (ov > bv0 || (ov == bv0 && oi < bi0)) { bv0 = ov; bi0 = oi; }
            ov = __shfl_xor_sync(0xffffffffu, bv1, off);
            oi = __shfl_xor_sync(0xffffffffu, bi1, off);
            if (ov > bv1 || (ov == bv1 && oi < bi1)) { bv1 = ov; bi1 = oi; }
        }
        if (lc == 0) {
            int r0 = wm * 32 + mt * 16 + lr;
            spm[wn * 128 + r0] = bv0;  spi[wn * 128 + r0] = bi0;
            spm[wn * 128 + r0 + 8] = bv1; spi[wn * 128 + r0 + 8] = bi1;
        }
    }
    __syncthreads();
    if (tid < 128) {
        float v0 = spm[tid], v1 = spm[128 + tid];
        int   i0 = spi[tid], i1 = spi[128 + tid];
        if (v1 > v0) { v0 = v1; i0 = i1; }
        g_pmax[(b * 8 + dt) * NSRC + st * 128 + tid] = v0;
        g_pidx[(b * 8 + dt) * NSRC + st * 128 + tid] = i0;
    }
}

// ---------------- 3. top-k: hybrid smem/shfl bitonic ----------------
__global__ void topk_k() {
    __shared__ unsigned long long key[1024];
    __shared__ int nidx[1024];
    __shared__ int mrg[1024];
    __shared__ int scn[1024];
    int b = blockIdx.x, tid = threadIdx.x;   // 1024

    float bv = g_pmax[(b * 8) * NSRC + tid];
    int   bi = g_pidx[(b * 8) * NSRC + tid];
#pragma unroll
    for (int dt = 1; dt < 8; dt++) {
        float v = g_pmax[(b * 8 + dt) * NSRC + tid];
        if (v > bv) { bv = v; bi = g_pidx[(b * 8 + dt) * NSRC + tid]; }
    }
    nidx[tid] = bi;
    unsigned long long kv;
    {
        unsigned u = __float_as_uint(bv);
        u = (u & 0x80000000u) ? ~u : (u | 0x80000000u);
        kv = ((unsigned long long)(~u) << 32) | (unsigned)tid;
    }
    mrg[tid] = 0;
    g_lhead[b * NSRC + tid] = -1;

    for (int k = 2; k <= 1024; k <<= 1) {
        int j = k >> 1;
        if (j > 16) {      // smem phases (in-place owner-swap, 1 sync each)
            key[tid] = kv;
            __syncthreads();
            for (; j > 16; j >>= 1) {
                int p = tid ^ j;
                if (p > tid) {
                    bool up = ((tid & k) == 0);
                    unsigned long long a = key[tid], c2 = key[p];
                    if ((a > c2) == up) { key[tid] = c2; key[p] = a; }
                }
                __syncthreads();
            }
            kv = key[tid];
        }
        for (; j > 0; j >>= 1) {   // warp-register phases, no syncs
            unsigned long long other = __shfl_xor_sync(0xffffffffu, kv, j);
            bool up = ((tid & k) == 0);
            bool iLower = ((tid & j) == 0);
            bool takeMin = (up == iLower);
            kv = (takeMin == (kv < other)) ? kv : other;
        }
    }
    // kv = sorted key at rank tid (ascending key = descending value, tie asc idx)
    if (tid < 512) {
        int s = (int)(kv & 0xffffffffu);
        g_srcidx[b * RR + tid] = s;
        mrg[s] = 1;
        int d = nidx[s];
        g_lnext[b * RR + tid] = atomicExch(&g_lhead[b * NSRC + d], tid);
    }
    __syncthreads();
    int um = mrg[tid] ? 0 : 1;
    scn[tid] = um; __syncthreads();
    for (int off = 1; off < 1024; off <<= 1) {
        int v = scn[tid];
        int v2 = (tid >= off) ? scn[tid - off] : 0;
        __syncthreads();
        scn[tid] = v + v2; __syncthreads();
    }
    if (um) g_unmidx[b * RR + (scn[tid] - 1)] = tid;
}

// ---------------- 4. fused merge build (emits fp16 xm) ----------------
__global__ void buildall_k(const float* __restrict__ x) {
    int row = blockIdx.x;
    int b = row / MM, j = row - b * MM;
    int t = threadIdx.x;                    // 192
    __half* dst = g_xm + (size_t)row * CC;
    if (j >= NDST) {
        int s = g_unmidx[b * RR + (j - NDST)];
        const float* src = x + ((size_t)b * NN + 2 * s) * CC;
        float4 v = *(const float4*)&src[t * 4];
        uint2 o = { packh2(v.x, v.y), packh2(v.z, v.w) };
        *(uint2*)&dst[t * 4] = o;
        return;
    }
    const float* dsrc = x + ((size_t)b * NN + 2 * j + 1) * CC;
    float4 v = *(const float4*)&dsrc[t * 4];
    float cntf = 1.f;
    int it = g_lhead[b * NSRC + j];
    while (it >= 0) {
        int s = g_srcidx[b * RR + it];
        float4 sv = *(const float4*)&x[((size_t)b * NN + 2 * s) * CC + t * 4];
        v.x += sv.x; v.y += sv.y; v.z += sv.z; v.w += sv.w;
        cntf += 1.f;
        it = g_lnext[b * RR + it];
    }
    float inv = 1.f / cntf;
    uint2 o = { packh2(v.x * inv, v.y * inv), packh2(v.z * inv, v.w * inv) };
    *(uint2*)&dst[t * 4] = o;
}

// ---------------- 5. fp16 GEMM k16 (R14/R15-verified) ----------------
// mode 1: fp16 output. mode 2: fused-unmerge fp32 scatter to out.
__global__ __launch_bounds__(256, 2) void gemm_fp16_k(
        const __half* __restrict__ A, const __half* __restrict__ Bm,
        const float* __restrict__ bias, void* Cv, int Nd, int mode) {
    __shared__ __align__(16) char gsm[2 * 10240 + 2 * 8704];
    unsigned sA = smem_u32(gsm);
    unsigned sB = sA + 20480;
    int tid = threadIdx.x;
    int w = tid >> 5, l = tid & 31;
    int wm = w & 3, wn = w >> 2;
    int lr = l >> 2, lc = l & 3;
    int bm = blockIdx.y * 128, bn = blockIdx.x * 128;
    float acc[2][8][4] = {};

    int ar = tid >> 1, ah = tid & 1;
    const __half* Ap = A + (size_t)(bm + ar) * CC + ah * 16;
    unsigned adst = sA + (unsigned)(ar * 80 + ah * 32);
    int br = tid >> 3, bc = tid & 7;
    const __half* Bp = Bm + bn + bc * 16;
    unsigned bdst = sB + (unsigned)(br * 272 + bc * 32);

    unsigned aAdr = sA + (unsigned)((wm * 32 + (l & 15)) * 80 + ((l >> 4) & 1) * 16);
    unsigned bAdr = sB + (unsigned)(((l & 7) + ((l >> 3) & 1) * 8) * 272
                         + (wn * 64 + ((l >> 4) & 1) * 8) * 2);

    auto issue = [&](int c, int buf) {
        const __half* a = Ap + c * 32;
        cp16(adst + buf * 10240u, a);
        cp16(adst + buf * 10240u + 16, a + 8);
        const __half* bsrc = Bp + (size_t)(c * 32 + br) * Nd;
        cp16(bdst + buf * 8704u, bsrc);
        cp16(bdst + buf * 8704u + 16, bsrc + 8);
    };

    issue(0, 0); cpcommit();
    int buf = 0;
    for (int c = 0; c < 24; c++) {
        cpwait0();
        __syncthreads();
        if (c + 1 < 24) { issue(c + 1, buf ^ 1); cpcommit(); }
        unsigned ao = buf * 10240u, bo = buf * 8704u;
#pragma unroll
        for (int ks = 0; ks < 2; ks++) {
            unsigned a0[4], a1[4];
            ldsm4(a0, aAdr + ao + ks * 32);
            ldsm4(a1, aAdr + ao + 16 * 80 + ks * 32);
#pragma unroll
            for (int ntp = 0; ntp < 4; ntp++) {
                unsigned bq[4];
                ldsm4t(bq, bAdr + bo + ks * 16 * 272 + ntp * 32);
                mma16f(acc[0][2 * ntp],     a0, bq);
                mma16f(acc[1][2 * ntp],     a1, bq);
                mma16f(acc[0][2 * ntp + 1], a0, bq + 2);
                mma16f(acc[1][2 * ntp + 1], a1, bq + 2);
            }
        }
        buf ^= 1;
    }
    if (mode == 1) {
        __half* C = (__half*)Cv;
#pragma unroll
        for (int mt = 0; mt < 2; mt++) {
            int r0 = bm + wm * 32 + mt * 16 + lr;
#pragma unroll
            for (int nt = 0; nt < 8; nt++) {
                int c = bn + wn * 64 + nt * 8 + 2 * lc;
                float b0 = bias[c], b1 = bias[c + 1];
                *(unsigned*)&C[(size_t)r0 * Nd + c] =
                    packh2(acc[mt][nt][0] + b0, acc[mt][nt][1] + b1);
                *(unsigned*)&C[(size_t)(r0 + 8) * Nd + c] =
                    packh2(acc[mt][nt][2] + b0, acc[mt][nt][3] + b1);
            }
        }
    } else {
        float* outp = (float*)Cv;
        int b2 = bm / MM;
        float bx[8][2];
#pragma unroll
        for (int nt = 0; nt < 8; nt++) {
            int c = bn + wn * 64 + nt * 8 + 2 * lc;
            bx[nt][0] = bias[c]; bx[nt][1] = bias[c + 1];
        }
#pragma unroll
        for (int mt = 0; mt < 2; mt++) {
#pragma unroll
            for (int hf = 0; hf < 2; hf++) {
                int rrow = bm + wm * 32 + mt * 16 + lr + hf * 8;
                int j = rrow - b2 * MM;
                float v[8][2];
#pragma unroll
                for (int nt = 0; nt < 8; nt++) {
                    v[nt][0] = acc[mt][nt][2 * hf]     + bx[nt][0];
                    v[nt][1] = acc[mt][nt][2 * hf + 1] + bx[nt][1];
                }
                int n0 = (j < NDST) ? (2 * j + 1)
                                    : 2 * g_unmidx[b2 * RR + (j - NDST)];
                float* dp = outp + ((size_t)b2 * NN + n0) * CC + bn + wn * 64 + 2 * lc;
#pragma unroll
                for (int nt = 0; nt < 8; nt++)
                    *(float2*)&dp[nt * 8] = make_float2(v[nt][0], v[nt][1]);
                if (j < NDST) {
                    for (int it = g_lhead[b2 * NSRC + j]; it >= 0; it = g_lnext[b2 * RR + it]) {
                        int s = g_srcidx[b2 * RR + it];
                        float* dp2 = outp + ((size_t)b2 * NN + 2 * s) * CC + bn + wn * 64 + 2 * lc;
#pragma unroll
                        for (int nt = 0; nt < 8; nt++)
                            *(float2*)&dp2[nt * 8] = make_float2(v[nt][0], v[nt][1]);
                    }
                }
            }
        }
    }
}

// ---------------- 6. flash attention fp16 k16 (R14-verified, verbatim) ----------------
#define FL_SMEM (18432 + 2 * 9216 + 2 * 9216)
__global__ __launch_bounds__(256, 2) void flash_fp16_k(
        const __half* __restrict__ qkv, __half* __restrict__ o) {
    extern __shared__ char fsm[];
    unsigned sQ = smem_u32(fsm);
    unsigned sK = sQ + 18432;
    unsigned sV = sK + 2 * 9216;

    int qt = blockIdx.x, bh = blockIdx.y;
    int b = bh / HH, h = bh % HH;
    const __half* base = qkv + (size_t)b * MM * C3 + h * 64;
    int tid = threadIdx.x;
    int w = tid >> 5, l = tid & 31;
    int lr = l >> 2, lc = l & 3;
    int mr0 = w * 16 + lr;

    unsigned qAdr = sQ + (unsigned)((w * 16 + (l & 15)) * 144 + ((l >> 4) & 1) * 16);
    unsigned kAdr = sK + (unsigned)(((l & 7) + ((l >> 4) & 1) * 8) * 144 + ((l >> 3) & 1) * 16);
    unsigned vAdr = sV + (unsigned)(((l & 7) + ((l >> 3) & 1) * 8) * 144 + ((l >> 4) & 1) * 16);

    {
        int r = tid >> 1, hf = (tid & 1) * 32;
        const __half2* qp = (const __half2*)(base + (size_t)(qt * 128 + r) * C3 + hf);
        __half2* dq = (__half2*)(fsm + r * 144 + hf * 2);
        __half2 sc = __floats2half2_rn(0.125f, 0.125f);
#pragma unroll
        for (int i = 0; i < 16; i++) dq[i] = __hmul2(qp[i], sc);
    }
    int kr = tid >> 2, kq = (tid & 3) * 16;
    unsigned kdst = sK + (unsigned)(kr * 144 + (tid & 3) * 32);
    unsigned vdst = sV + (unsigned)(kr * 144 + (tid & 3) * 32);
    const __half* kgp = base + CC + (size_t)kr * C3 + kq;
    const __half* vgp = base + 2 * CC + (size_t)kr * C3 + kq;

    auto issue = [&](int kt, int buf) {
        const __half* ks = kgp + (size_t)kt * 64 * C3;
        const __half* vs = vgp + (size_t)kt * 64 * C3;
        cp16(kdst + buf * 9216u, ks);  cp16(kdst + buf * 9216u + 16, ks + 8);
        cp16(vdst + buf * 9216u, vs);  cp16(vdst + buf * 9216u + 16, vs + 8);
        cpcommit();
    };
    issue(0, 0);

    float om[8][4] = {};
    float m0 = -INFINITY, m1 = -INFINITY, l0 = 0.f, l1 = 0.f;

    for (int kt = 0; kt < 24; kt++) {
        int buf = kt & 1;
        cpwait0();
        __syncthreads();
        if (kt + 1 < 24) issue(kt + 1, buf ^ 1);
        float s[8][4] = {};
#pragma unroll
        for (int ks = 0; ks < 4; ks++) {
            unsigned af[4];
            ldsm4(af, qAdr + ks * 32);
#pragma unroll
            for (int ntp = 0; ntp < 4; ntp++) {
                unsigned bq[4];
                ldsm4(bq, kAdr + buf * 9216u + ntp * 2304 + ks * 32);
                mma16f(s[2 * ntp],     af, bq);
                mma16f(s[2 * ntp + 1], af, bq + 2);
            }
        }
        float mx0 = -INFINITY, mx1 = -INFINITY;
#pragma unroll
        for (int nt = 0; nt < 8; nt++) {
            mx0 = fmaxf(mx0, fmaxf(s[nt][0], s[nt][1]));
            mx1 = fmaxf(mx1, fmaxf(s[nt][2], s[nt][3]));
        }
        mx0 = fmaxf(mx0, __shfl_xor_sync(0xffffffffu, mx0, 1));
        mx0 = fmaxf(mx0, __shfl_xor_sync(0xffffffffu, mx0, 2));
        mx1 = fmaxf(mx1, __shfl_xor_sync(0xffffffffu, mx1, 1));
        mx1 = fmaxf(mx1, __shfl_xor_sync(0xffffffffu, mx1, 2));
        float mn0 = fmaxf(m0, mx0), mn1 = fmaxf(m1, mx1);
        float al0 = __expf(m0 - mn0), al1 = __expf(m1 - mn1);
        m0 = mn0; m1 = mn1;
        float rs0 = 0.f, rs1 = 0.f;
#pragma unroll
        for (int nt = 0; nt < 8; nt++) {
            s[nt][0] = __expf(s[nt][0] - mn0); rs0 += s[nt][0];
            s[nt][1] = __expf(s[nt][1] - mn0); rs0 += s[nt][1];
            s[nt][2] = __expf(s[nt][2] - mn1); rs1 += s[nt][2];
            s[nt][3] = __expf(s[nt][3] - mn1); rs1 += s[nt][3];
        }
        rs0 += __shfl_xor_sync(0xffffffffu, rs0, 1);
        rs0 += __shfl_xor_sync(0xffffffffu, rs0, 2);
        rs1 += __shfl_xor_sync(0xffffffffu, rs1, 1);
        rs1 += __shfl_xor_sync(0xffffffffu, rs1, 2);
        l0 = l0 * al0 + rs0; l1 = l1 * al1 + rs1;
#pragma unroll
        for (int nt = 0; nt < 8; nt++) {
            om[nt][0] *= al0; om[nt][1] *= al0;
            om[nt][2] *= al1; om[nt][3] *= al1;
        }
#pragma unroll
        for (int ks = 0; ks < 4; ks++) {
            unsigned af[4] = {
                packh2(s[2 * ks][0],     s[2 * ks][1]),
                packh2(s[2 * ks][2],     s[2 * ks][3]),
                packh2(s[2 * ks + 1][0], s[2 * ks + 1][1]),
                packh2(s[2 * ks + 1][2], s[2 * ks + 1][3])
            };
#pragma unroll
            for (int ntp = 0; ntp < 4; ntp++) {
                unsigned bq[4];
                ldsm4t(bq, vAdr + buf * 9216u + ks * 2304 + ntp * 32);
                mma16f(om[2 * ntp],     af, bq);
                mma16f(om[2 * ntp + 1], af, bq + 2);
            }
        }
    }
    float i0 = 1.f / l0, i1 = 1.f / l1;
    size_t row0 = (size_t)b * MM + qt * 128 + mr0;
#pragma unroll
    for (int nt = 0; nt < 8; nt++) {
        int c = h * 64 + nt * 8 + 2 * lc;
        *(unsigned*)&o[row0 * CC + c] = packh2(om[nt][0] * i0, om[nt][1] * i0);
        *(unsigned*)&o[(row0 + 8) * CC + c] = packh2(om[nt][2] * i1, om[nt][3] * i1);
    }
}

// ---------------- launcher ----------------
extern "C" void kernel_launch(void* const* d_in, const int* in_sizes, int n_in,
                              void* d_out, int out_size) {
    const float* x    = (const float*)d_in[0];
    const float* Wqkv = (const float*)d_in[1];
    const float* bqkv = (const float*)d_in[2];
    const float* Wo   = (const float*)d_in[3];
    const float* bo   = (const float*)d_in[4];
    float* out = (float*)d_out;

    __half *xm, *qkvb, *attnb, *wq, *wo;
    cudaGetSymbolAddress((void**)&xm, g_xm);
    cudaGetSymbolAddress((void**)&qkvb, g_qkv);
    cudaGetSymbolAddress((void**)&attnb, g_attn);
    cudaGetSymbolAddress((void**)&wq, g_wqkv);
    cudaGetSymbolAddress((void**)&wo, g_wo);

    cudaFuncSetAttribute(match_mma_k, cudaFuncAttributeMaxDynamicSharedMemorySize, 49152);
    cudaFuncSetAttribute(flash_fp16_k, cudaFuncAttributeMaxDynamicSharedMemorySize, FL_SMEM);

    int nw = CC * C3 + CC * CC;
    roundboth_k<<<(nw + 255) / 256, 256>>>(Wqkv, wq, CC * C3, Wo, wo, CC * CC);
    metric_k<<<BB * NN / 8, 256>>>(x);
    match_mma_k<<<dim3(8, 8, 8), 256, 49152>>>();
    topk_k<<<BB, 1024>>>();
    buildall_k<<<BB * MM, 192>>>(x);
    gemm_fp16_k<<<dim3(C3 / 128, (BB * MM) / 128), 256>>>(xm, wq, bqkv, (void*)qkvb, C3, 1);
    flash_fp16_k<<<dim3(MM / 128, BB * HH), 256, FL_SMEM>>>(qkvb, attnb);
    gemm_fp16_k<<<dim3(CC / 128, (BB * MM) / 128), 256>>>(attnb, wo, bo, (void*)out, CC, 2);
}